// round 1
// baseline (speedup 1.0000x reference)
#include <cuda_runtime.h>
#include <cuda_bf16.h>
#include <math.h>

// ---------------------------------------------------------------------------
// Model constants
// ---------------------------------------------------------------------------
#define Lc 2
#define Hc 2048
#define NHc 32
#define NKVc 4
#define HDc 64
#define Ic 5632
#define Bc 2
#define Sc 1024
#define Tc (Bc * Sc)            // 2048 tokens
#define QKVN ((NHc + 2 * NKVc) * HDc)  // 2560
#define GUN (2 * Ic)            // 11264
#define EPSc 1e-5f

// ---------------------------------------------------------------------------
// Scratch (static device globals; no allocation allowed)
// ---------------------------------------------------------------------------
__device__ float g_res [Tc * Hc];
__device__ float g_hn  [Tc * Hc];
__device__ float g_qkv [Tc * QKVN];
__device__ float g_kc  [Bc * NKVc * Sc * HDc];
__device__ float g_vc  [Bc * NKVc * Sc * HDc];
__device__ float g_attn[Tc * Hc];
__device__ float g_gu  [(size_t)Tc * GUN];
__device__ float g_act [(size_t)Tc * Ic];
__device__ float g_h   [Tc * Hc];

// ---------------------------------------------------------------------------
// Embedding gather: res[t,:] = embed[ids[t],:]
// ---------------------------------------------------------------------------
__global__ void embed_kernel(const int* __restrict__ ids,
                             const float* __restrict__ embed,
                             float* __restrict__ res) {
    int t = blockIdx.x;
    int id = ids[t];
    const float4* src = (const float4*)(embed + (size_t)id * Hc);
    float4* dst = (float4*)(res + (size_t)t * Hc);
    for (int i = threadIdx.x; i < Hc / 4; i += blockDim.x)
        dst[i] = src[i];
}

// ---------------------------------------------------------------------------
// Fused (optional residual add) + RMSNorm.
// if add != nullptr: res += add (stored back), then out = rmsnorm(res)*w
// ---------------------------------------------------------------------------
__global__ void addnorm_kernel(float* __restrict__ res,
                               const float* __restrict__ add,
                               const float* __restrict__ w,
                               float* __restrict__ out) {
    int t = blockIdx.x;
    int tid = threadIdx.x;
    float* rp = res + (size_t)t * Hc;
    float vals[8];
    float ss = 0.f;
#pragma unroll
    for (int i = 0; i < 8; i++) {
        int idx = tid + i * 256;
        float v = rp[idx];
        if (add) { v += add[(size_t)t * Hc + idx]; rp[idx] = v; }
        vals[i] = v;
        ss += v * v;
    }
    // block reduce
    __shared__ float warp_s[8];
#pragma unroll
    for (int off = 16; off > 0; off >>= 1)
        ss += __shfl_down_sync(0xffffffff, ss, off);
    if ((tid & 31) == 0) warp_s[tid >> 5] = ss;
    __syncthreads();
    if (tid < 8) {
        float v = warp_s[tid];
#pragma unroll
        for (int off = 4; off > 0; off >>= 1)
            v += __shfl_down_sync(0xff, v, off);
        if (tid == 0) warp_s[0] = v;
    }
    __syncthreads();
    float inv = rsqrtf(warp_s[0] * (1.0f / Hc) + EPSc);
#pragma unroll
    for (int i = 0; i < 8; i++) {
        int idx = tid + i * 256;
        out[(size_t)t * Hc + idx] = vals[i] * inv * w[idx];
    }
}

// ---------------------------------------------------------------------------
// SGEMM: C[M,N] = A[M,K] @ B[K,N]   (+ addend if non-null)
// Tiles 128x128x8, 256 threads, 8x8 microtile. Dims must divide tiles.
// ---------------------------------------------------------------------------
#define BM 128
#define BN 128
#define BK 8
__global__ void __launch_bounds__(256)
sgemm_kernel(const float* __restrict__ A, const float* __restrict__ B,
             float* __restrict__ C, const float* __restrict__ addend,
             int M, int N, int K) {
    __shared__ __align__(16) float As[BK][BM];
    __shared__ __align__(16) float Bs[BK][BN];

    int bx = blockIdx.x;   // N tile
    int by = blockIdx.y;   // M tile
    int tid = threadIdx.x;
    int tRow = tid / 16;   // 0..15
    int tCol = tid % 16;   // 0..15

    const float* Ab = A + (size_t)by * BM * K;
    const float* Bb = B + (size_t)bx * BN;

    int aRow = tid >> 1;          // 0..127
    int aCol = (tid & 1) * 4;     // 0 or 4
    int bRow = tid >> 5;          // 0..7
    int bCol = (tid & 31) * 4;    // 0..124

    float acc[8][8];
#pragma unroll
    for (int i = 0; i < 8; i++)
#pragma unroll
        for (int j = 0; j < 8; j++) acc[i][j] = 0.f;

    for (int k0 = 0; k0 < K; k0 += BK) {
        float4 a4 = *(const float4*)(Ab + (size_t)aRow * K + k0 + aCol);
        As[aCol + 0][aRow] = a4.x;
        As[aCol + 1][aRow] = a4.y;
        As[aCol + 2][aRow] = a4.z;
        As[aCol + 3][aRow] = a4.w;
        float4 b4 = *(const float4*)(Bb + (size_t)(k0 + bRow) * N + bCol);
        *(float4*)&Bs[bRow][bCol] = b4;
        __syncthreads();

#pragma unroll
        for (int k = 0; k < BK; k++) {
            float af[8], bf[8];
            *(float4*)&af[0] = *(const float4*)&As[k][tRow * 8];
            *(float4*)&af[4] = *(const float4*)&As[k][tRow * 8 + 4];
            *(float4*)&bf[0] = *(const float4*)&Bs[k][tCol * 8];
            *(float4*)&bf[4] = *(const float4*)&Bs[k][tCol * 8 + 4];
#pragma unroll
            for (int i = 0; i < 8; i++)
#pragma unroll
                for (int j = 0; j < 8; j++)
                    acc[i][j] = fmaf(af[i], bf[j], acc[i][j]);
        }
        __syncthreads();
    }

    // epilogue
#pragma unroll
    for (int i = 0; i < 8; i++) {
        size_t row = (size_t)(by * BM + tRow * 8 + i);
        size_t base = row * N + bx * BN + tCol * 8;
#pragma unroll
        for (int j4 = 0; j4 < 2; j4++) {
            float4 v;
            v.x = acc[i][j4 * 4 + 0];
            v.y = acc[i][j4 * 4 + 1];
            v.z = acc[i][j4 * 4 + 2];
            v.w = acc[i][j4 * 4 + 3];
            if (addend) {
                float4 a = *(const float4*)(addend + base + j4 * 4);
                v.x += a.x; v.y += a.y; v.z += a.z; v.w += a.w;
            }
            *(float4*)(C + base + j4 * 4) = v;
        }
    }
}

// ---------------------------------------------------------------------------
// RoPE (in-place for Q inside qkv; K scattered to kcache; V copied to vcache)
// qkv layout per token: [ q(32*64) | k(4*64) | v(4*64) ]
// kcache/vcache layout: [B, NKV, S, HD]
// ---------------------------------------------------------------------------
__global__ void rope_kernel(float* __restrict__ qkv,
                            const int* __restrict__ pos,
                            float* __restrict__ kc,
                            float* __restrict__ vc) {
    int t = blockIdx.x;
    int b = t / Sc, s = t % Sc;
    int tid = threadIdx.x;
    float p = (float)pos[s];
    const float lt = logf(10000.f) / 32.f;

    for (int w = tid; w < (NHc + NKVc) * 32; w += blockDim.x) {
        int head = w / 32, j = w % 32;
        float ang = p * __expf(-(float)j * lt);
        float c = cosf(ang), sn = sinf(ang);
        if (head < NHc) {
            float* base = qkv + (size_t)t * QKVN + head * HDc;
            float x1 = base[j], x2 = base[j + 32];
            base[j]      = x1 * c - x2 * sn;
            base[j + 32] = x2 * c + x1 * sn;
        } else {
            int hk = head - NHc;
            const float* base = qkv + (size_t)t * QKVN + NHc * HDc + hk * HDc;
            float x1 = base[j], x2 = base[j + 32];
            float* kb = kc + (((size_t)(b * NKVc + hk)) * Sc + s) * HDc;
            kb[j]      = x1 * c - x2 * sn;
            kb[j + 32] = x2 * c + x1 * sn;
        }
    }
    for (int w = tid; w < NKVc * HDc; w += blockDim.x) {
        int hv = w / HDc, d = w % HDc;
        vc[(((size_t)(b * NKVc + hv)) * Sc + s) * HDc + d] =
            qkv[(size_t)t * QKVN + (NHc + NKVc) * HDc + hv * HDc + d];
    }
}

// ---------------------------------------------------------------------------
// Flash attention (causal, fp32). One block = 64 queries of one (b, head).
// Output layout: attn[b*S + q][h*64 + d]  (token-major for the O projection)
// ---------------------------------------------------------------------------
#define FPAD 68
struct __align__(16) FlashSmem {
    float Qs[64][FPAD];   // [d][q], pre-scaled
    float Ks[64][FPAD];   // [d][k]
    float Vs[64][FPAD];   // [k][d]
    float Ss[64][FPAD];   // [k][q]  (scores, then P)
    float mrow[64];
    float lrow[64];
    float arow[64];
};

__global__ void __launch_bounds__(256)
flash_kernel(const float* __restrict__ qbuf,
             const float* __restrict__ kc,
             const float* __restrict__ vc,
             float* __restrict__ attn) {
    extern __shared__ char smem_raw[];
    FlashSmem& sm = *reinterpret_cast<FlashSmem*>(smem_raw);

    int qb = blockIdx.x;          // query tile (16)
    int h  = blockIdx.y;          // head (32)
    int b  = blockIdx.z;          // batch (2)
    int hkv = h / (NHc / NKVc);
    int tid = threadIdx.x;
    int ty = tid / 16, tx = tid % 16;
    const float scale = 0.125f;   // 1/sqrt(64)

    // Load Q tile transposed ([d][q]) and pre-scale
#pragma unroll
    for (int r = 0; r < 4; r++) {
        int row = (tid / 16) + r * 16;     // q local
        int col = (tid % 16) * 4;          // d
        const float* src = qbuf + ((size_t)(b * Sc + qb * 64 + row)) * QKVN + h * HDc + col;
        float4 v = *(const float4*)src;
        sm.Qs[col + 0][row] = v.x * scale;
        sm.Qs[col + 1][row] = v.y * scale;
        sm.Qs[col + 2][row] = v.z * scale;
        sm.Qs[col + 3][row] = v.w * scale;
    }
    if (tid < 64) { sm.mrow[tid] = -1e30f; sm.lrow[tid] = 0.f; }

    float oacc[4][4];
#pragma unroll
    for (int i = 0; i < 4; i++)
#pragma unroll
        for (int j = 0; j < 4; j++) oacc[i][j] = 0.f;

    __syncthreads();

    for (int kb = 0; kb <= qb; kb++) {
        // Load K (transposed [d][k]) and V ([k][d])
#pragma unroll
        for (int r = 0; r < 4; r++) {
            int row = (tid / 16) + r * 16;   // key local
            int col = (tid % 16) * 4;        // d
            size_t kvbase = (((size_t)(b * NKVc + hkv)) * Sc + kb * 64 + row) * HDc + col;
            float4 k4 = *(const float4*)(kc + kvbase);
            sm.Ks[col + 0][row] = k4.x;
            sm.Ks[col + 1][row] = k4.y;
            sm.Ks[col + 2][row] = k4.z;
            sm.Ks[col + 3][row] = k4.w;
            *(float4*)&sm.Vs[row][col] = *(const float4*)(vc + kvbase);
        }
        __syncthreads();

        // S = Q . K^T
        float sacc[4][4];
#pragma unroll
        for (int i = 0; i < 4; i++)
#pragma unroll
            for (int j = 0; j < 4; j++) sacc[i][j] = 0.f;
#pragma unroll 8
        for (int d = 0; d < 64; d++) {
            float qf[4], kf[4];
            *(float4*)qf = *(const float4*)&sm.Qs[d][ty * 4];
            *(float4*)kf = *(const float4*)&sm.Ks[d][tx * 4];
#pragma unroll
            for (int i = 0; i < 4; i++)
#pragma unroll
                for (int j = 0; j < 4; j++)
                    sacc[i][j] = fmaf(qf[i], kf[j], sacc[i][j]);
        }
        // causal mask only on the diagonal tile
        if (kb == qb) {
#pragma unroll
            for (int i = 0; i < 4; i++)
#pragma unroll
                for (int j = 0; j < 4; j++)
                    if (tx * 4 + j > ty * 4 + i) sacc[i][j] = -1e30f;
        }
        // Store S transposed ([k][q])
#pragma unroll
        for (int i = 0; i < 4; i++)
#pragma unroll
            for (int j = 0; j < 4; j++)
                sm.Ss[tx * 4 + j][ty * 4 + i] = sacc[i][j];
        __syncthreads();

        // Online softmax row stats (one thread per query row)
        if (tid < 64) {
            int q = tid;
            float m_old = sm.mrow[q];
            float m = m_old;
#pragma unroll 8
            for (int k = 0; k < 64; k++) m = fmaxf(m, sm.Ss[k][q]);
            float alpha = __expf(m_old - m);
            float ls = 0.f;
#pragma unroll 8
            for (int k = 0; k < 64; k++) {
                float pv = __expf(sm.Ss[k][q] - m);
                sm.Ss[k][q] = pv;
                ls += pv;
            }
            sm.mrow[q] = m;
            sm.lrow[q] = sm.lrow[q] * alpha + ls;
            sm.arow[q] = alpha;
        }
        __syncthreads();

        // O = O*alpha + P @ V
        float al[4];
#pragma unroll
        for (int i = 0; i < 4; i++) al[i] = sm.arow[ty * 4 + i];
#pragma unroll
        for (int i = 0; i < 4; i++)
#pragma unroll
            for (int j = 0; j < 4; j++) oacc[i][j] *= al[i];
#pragma unroll 8
        for (int k = 0; k < 64; k++) {
            float pf[4], vf[4];
            *(float4*)pf = *(const float4*)&sm.Ss[k][ty * 4];
            *(float4*)vf = *(const float4*)&sm.Vs[k][tx * 4];
#pragma unroll
            for (int i = 0; i < 4; i++)
#pragma unroll
                for (int j = 0; j < 4; j++)
                    oacc[i][j] = fmaf(pf[i], vf[j], oacc[i][j]);
        }
        __syncthreads();  // protect Ks/Vs/Ss for next iteration
    }

    // Normalize + write out
#pragma unroll
    for (int i = 0; i < 4; i++) {
        float inv = 1.0f / sm.lrow[ty * 4 + i];
        int q = qb * 64 + ty * 4 + i;
        float4 o;
        o.x = oacc[i][0] * inv;
        o.y = oacc[i][1] * inv;
        o.z = oacc[i][2] * inv;
        o.w = oacc[i][3] * inv;
        *(float4*)&attn[((size_t)(b * Sc + q)) * (NHc * HDc) + h * HDc + tx * 4] = o;
    }
}

// ---------------------------------------------------------------------------
// SwiGLU: act[t,i] = silu(gu[t,i]) * gu[t,I+i]
// ---------------------------------------------------------------------------
__global__ void swiglu_kernel(const float* __restrict__ gu, float* __restrict__ act) {
    size_t e = (size_t)blockIdx.x * blockDim.x + threadIdx.x;
    size_t t = e / Ic;
    size_t i = e % Ic;
    float g = gu[t * GUN + i];
    float u = gu[t * GUN + Ic + i];
    float sig = 1.0f / (1.0f + __expf(-g));
    act[e] = g * sig * u;
}

// ---------------------------------------------------------------------------
// Launch
// ---------------------------------------------------------------------------
extern "C" void kernel_launch(void* const* d_in, const int* in_sizes, int n_in,
                              void* d_out, int out_size) {
    const int*   input_ids = (const int*)d_in[0];
    const int*   positions = (const int*)d_in[1];
    const float* embed     = (const float*)d_in[2];
    const float* w_qkv     = (const float*)d_in[3];
    const float* w_o       = (const float*)d_in[4];
    const float* w_gate_up = (const float*)d_in[5];
    const float* w_down    = (const float*)d_in[6];
    const float* ln1_w     = (const float*)d_in[7];
    const float* ln2_w     = (const float*)d_in[8];
    const float* norm_w    = (const float*)d_in[9];
    float* out = (float*)d_out;

    float *res, *hn, *qkv, *kc, *vc, *attn, *gu, *act, *hbuf;
    cudaGetSymbolAddress((void**)&res,  g_res);
    cudaGetSymbolAddress((void**)&hn,   g_hn);
    cudaGetSymbolAddress((void**)&qkv,  g_qkv);
    cudaGetSymbolAddress((void**)&kc,   g_kc);
    cudaGetSymbolAddress((void**)&vc,   g_vc);
    cudaGetSymbolAddress((void**)&attn, g_attn);
    cudaGetSymbolAddress((void**)&gu,   g_gu);
    cudaGetSymbolAddress((void**)&act,  g_act);
    cudaGetSymbolAddress((void**)&hbuf, g_h);

    int flash_smem = (int)sizeof(FlashSmem);
    cudaFuncSetAttribute(flash_kernel, cudaFuncAttributeMaxDynamicSharedMemorySize, flash_smem);

    embed_kernel<<<Tc, 256>>>(input_ids, embed, res);

    for (int l = 0; l < Lc; l++) {
        // residual (+= h from previous MLP) and ln1
        addnorm_kernel<<<Tc, 256>>>(res, l == 0 ? nullptr : hbuf, ln1_w + (size_t)l * Hc, hn);

        // QKV projection
        sgemm_kernel<<<dim3(QKVN / BN, Tc / BM), 256>>>(
            hn, w_qkv + (size_t)l * Hc * QKVN, qkv, nullptr, Tc, QKVN, Hc);

        // RoPE + KV scatter
        rope_kernel<<<Tc, 128>>>(qkv, positions, kc, vc);

        // Attention
        flash_kernel<<<dim3(Sc / 64, NHc, Bc), 256, flash_smem>>>(qkv, kc, vc, attn);

        // O projection fused with residual add
        sgemm_kernel<<<dim3(Hc / BN, Tc / BM), 256>>>(
            attn, w_o + (size_t)l * Hc * Hc, res, res, Tc, Hc, Hc);

        // ln2
        addnorm_kernel<<<Tc, 256>>>(res, nullptr, ln2_w + (size_t)l * Hc, hn);

        // gate_up projection
        sgemm_kernel<<<dim3(GUN / BN, Tc / BM), 256>>>(
            hn, w_gate_up + (size_t)l * Hc * GUN, gu, nullptr, Tc, GUN, Hc);

        // SwiGLU
        swiglu_kernel<<<(Tc * (size_t)Ic) / 256, 256>>>(gu, act);

        // down projection -> h
        sgemm_kernel<<<dim3(Hc / BN, Tc / BM), 256>>>(
            act, w_down + (size_t)l * Ic * Hc, hbuf, nullptr, Tc, Hc, Ic);
    }

    // final residual add + norm -> out
    addnorm_kernel<<<Tc, 256>>>(res, hbuf, norm_w, out);
}

// round 4
// speedup vs baseline: 2.1068x; 2.1068x over previous
#include <cuda_runtime.h>
#include <cuda_bf16.h>
#include <math.h>
#include <stdint.h>

// ---------------------------------------------------------------------------
// Model constants
// ---------------------------------------------------------------------------
#define Lc 2
#define Hc 2048
#define NHc 32
#define NKVc 4
#define HDc 64
#define Ic 5632
#define Bc 2
#define Sc 1024
#define Tc (Bc * Sc)                   // 2048 tokens
#define QKVN ((NHc + 2 * NKVc) * HDc)  // 2560
#define GUN (2 * Ic)                   // 11264
#define EPSc 1e-5f

// ---------------------------------------------------------------------------
// Scratch (static device globals; no allocation allowed)
// ---------------------------------------------------------------------------
__device__ float g_res [Tc * Hc];
__device__ float g_qkv [Tc * QKVN];
__device__ float g_kc  [Bc * NKVc * Sc * HDc];
__device__ float g_vc  [Bc * NKVc * Sc * HDc];
__device__ float g_gu  [(size_t)Tc * GUN];
__device__ float g_h   [Tc * Hc];

// split activations (GEMM A operands)
__device__ __nv_bfloat16 g_hn_hi [Tc * Hc];
__device__ __nv_bfloat16 g_hn_lo [Tc * Hc];
__device__ __nv_bfloat16 g_at_hi [Tc * Hc];
__device__ __nv_bfloat16 g_at_lo [Tc * Hc];
__device__ __nv_bfloat16 g_ac_hi [(size_t)Tc * Ic];
__device__ __nv_bfloat16 g_ac_lo [(size_t)Tc * Ic];

// Transposed split weights: per layer [qkv_t(QKVN,H) | o_t(H,H) | gu_t(GUN,H) | down_t(H,I)]
#define WT_QKV_OFF 0
#define WT_O_OFF   ((size_t)QKVN * Hc)
#define WT_GU_OFF  (WT_O_OFF + (size_t)Hc * Hc)
#define WT_DN_OFF  (WT_GU_OFF + (size_t)GUN * Hc)
#define WT_PER_L   (WT_DN_OFF + (size_t)Hc * Ic)
__device__ __nv_bfloat16 g_wt_hi[2 * WT_PER_L];
__device__ __nv_bfloat16 g_wt_lo[2 * WT_PER_L];

// ---------------------------------------------------------------------------
// Helpers
// ---------------------------------------------------------------------------
__device__ __forceinline__ void split2(float x, __nv_bfloat16& hi, __nv_bfloat16& lo) {
    hi = __float2bfloat16(x);
    lo = __float2bfloat16(x - __bfloat162float(hi));
}

__device__ __forceinline__ uint32_t smem_u32(const void* p) {
    uint32_t a;
    asm("{ .reg .u64 t; cvta.to.shared.u64 t, %1; cvt.u32.u64 %0, t; }"
        : "=r"(a) : "l"(p));
    return a;
}

__device__ __forceinline__ void cp_async16(uint32_t smem_addr, const void* gptr) {
    asm volatile("cp.async.cg.shared.global [%0], [%1], 16;"
                 :: "r"(smem_addr), "l"(gptr) : "memory");
}
#define CP_COMMIT() asm volatile("cp.async.commit_group;" ::: "memory")
#define CP_WAIT0()  asm volatile("cp.async.wait_group 0;" ::: "memory")

__device__ __forceinline__ void mma_bf16(float* d, const uint32_t* a, const uint32_t* b) {
    asm volatile(
        "mma.sync.aligned.m16n8k16.row.col.f32.bf16.bf16.f32 "
        "{%0,%1,%2,%3}, {%4,%5,%6,%7}, {%8,%9}, {%0,%1,%2,%3};"
        : "+f"(d[0]), "+f"(d[1]), "+f"(d[2]), "+f"(d[3])
        : "r"(a[0]), "r"(a[1]), "r"(a[2]), "r"(a[3]),
          "r"(b[0]), "r"(b[1]));
}

// ---------------------------------------------------------------------------
// Weight transpose + bf16x2 split: src[K,N] -> hi/lo[N,K]
// ---------------------------------------------------------------------------
__global__ void transpose_split(const float* __restrict__ src,
                                __nv_bfloat16* __restrict__ hi,
                                __nv_bfloat16* __restrict__ lo,
                                int K, int N) {
    __shared__ float tile[32][33];
    int nb = blockIdx.x * 32;
    int kb = blockIdx.y * 32;
#pragma unroll
    for (int i = threadIdx.y; i < 32; i += 8)
        tile[i][threadIdx.x] = src[(size_t)(kb + i) * N + nb + threadIdx.x];
    __syncthreads();
#pragma unroll
    for (int i = threadIdx.y; i < 32; i += 8) {
        float v = tile[threadIdx.x][i];
        __nv_bfloat16 h, l;
        split2(v, h, l);
        size_t idx = (size_t)(nb + i) * K + kb + threadIdx.x;
        hi[idx] = h;
        lo[idx] = l;
    }
}

// ---------------------------------------------------------------------------
// bf16x2 split GEMM: C[M,N] = A[M,K] @ Bt[N,K]^T (+ addend)
// A,B given as hi/lo bf16 arrays (K-major). 3 MMAs per tile-pair:
//   Ahi*Bhi + Ahi*Blo + Alo*Bhi  (fp32 accum)
// Block 128x128, BK=32, 256 threads (8 warps, 32x64 each).
// ---------------------------------------------------------------------------
#define PITCHB 80                 // bytes per smem row (32 bf16 = 64B + 16B pad)
#define PITCHW 20                 // words per smem row
#define ABYTES (128 * PITCHB)     // 10240 per operand array
#define BUFB   (4 * ABYTES)       // 40960 per buffer
#define GEMM_SMEM (2 * BUFB)      // 81920

__global__ void __launch_bounds__(256, 1)
gemm_bf16x2(const __nv_bfloat16* __restrict__ Ahi,
            const __nv_bfloat16* __restrict__ Alo,
            const __nv_bfloat16* __restrict__ Bhi,
            const __nv_bfloat16* __restrict__ Blo,
            float* __restrict__ C, const float* __restrict__ addend,
            int M, int N, int K) {
    extern __shared__ char smraw[];
    uint32_t sbase = smem_u32(smraw);
    const uint32_t* smw = (const uint32_t*)smraw;

    const int tid  = threadIdx.x;
    const int warp = tid >> 5;
    const int lane = tid & 31;
    const int wm   = (warp >> 1) * 32;   // warp M offset (0,32,64,96)
    const int wn   = (warp & 1) * 64;    // warp N offset (0,64)
    const int grp  = lane >> 2;          // 0..7
    const int tig  = lane & 3;           // 0..3

    const int m0 = blockIdx.x * 128;
    const int n0 = blockIdx.y * 128;

    // staging: each thread owns 2 chunks of 16B per operand array
    const int r0 = tid >> 2;            // 0..63
    const int cc = tid & 3;             // 16B chunk within row
    const size_t gA0 = (size_t)(m0 + r0) * K + cc * 8;
    const size_t gA1 = gA0 + (size_t)64 * K;
    const size_t gB0 = (size_t)(n0 + r0) * K + cc * 8;
    const size_t gB1 = gB0 + (size_t)64 * K;
    const uint32_t s0 = (uint32_t)r0 * PITCHB + cc * 16;
    const uint32_t s1 = s0 + 64 * PITCHB;

    const int nkt = K >> 5;

    float c[2][8][4];
#pragma unroll
    for (int mt = 0; mt < 2; mt++)
#pragma unroll
        for (int nt = 0; nt < 8; nt++)
#pragma unroll
            for (int i = 0; i < 4; i++) c[mt][nt][i] = 0.f;

    // prologue: stage tile 0 into buffer 0
    {
        uint32_t b = sbase;
        cp_async16(b + s0,              Ahi + gA0);
        cp_async16(b + s1,              Ahi + gA1);
        cp_async16(b + ABYTES + s0,     Alo + gA0);
        cp_async16(b + ABYTES + s1,     Alo + gA1);
        cp_async16(b + 2*ABYTES + s0,   Bhi + gB0);
        cp_async16(b + 2*ABYTES + s1,   Bhi + gB1);
        cp_async16(b + 3*ABYTES + s0,   Blo + gB0);
        cp_async16(b + 3*ABYTES + s1,   Blo + gB1);
        CP_COMMIT();
    }

    for (int kt = 0; kt < nkt; kt++) {
        CP_WAIT0();
        __syncthreads();

        if (kt + 1 < nkt) {
            uint32_t b = sbase + (uint32_t)((kt + 1) & 1) * BUFB;
            size_t ko = (size_t)(kt + 1) * 32;
            cp_async16(b + s0,              Ahi + gA0 + ko);
            cp_async16(b + s1,              Ahi + gA1 + ko);
            cp_async16(b + ABYTES + s0,     Alo + gA0 + ko);
            cp_async16(b + ABYTES + s1,     Alo + gA1 + ko);
            cp_async16(b + 2*ABYTES + s0,   Bhi + gB0 + ko);
            cp_async16(b + 2*ABYTES + s1,   Bhi + gB1 + ko);
            cp_async16(b + 3*ABYTES + s0,   Blo + gB0 + ko);
            cp_async16(b + 3*ABYTES + s1,   Blo + gB1 + ko);
            CP_COMMIT();
        }

        const uint32_t* sAhi = smw + (size_t)(kt & 1) * (BUFB / 4);
        const uint32_t* sAlo = sAhi + ABYTES / 4;
        const uint32_t* sBhi = sAlo + ABYTES / 4;
        const uint32_t* sBlo = sBhi + ABYTES / 4;

#pragma unroll
        for (int ks = 0; ks < 2; ks++) {
            uint32_t ahi[2][4], alo[2][4], bhi[8][2], blo[8][2];
#pragma unroll
            for (int mt = 0; mt < 2; mt++) {
                int rb = (wm + mt * 16 + grp) * PITCHW + ks * 8 + tig;
                ahi[mt][0] = sAhi[rb];
                ahi[mt][1] = sAhi[rb + 8 * PITCHW];
                ahi[mt][2] = sAhi[rb + 4];
                ahi[mt][3] = sAhi[rb + 8 * PITCHW + 4];
                alo[mt][0] = sAlo[rb];
                alo[mt][1] = sAlo[rb + 8 * PITCHW];
                alo[mt][2] = sAlo[rb + 4];
                alo[mt][3] = sAlo[rb + 8 * PITCHW + 4];
            }
#pragma unroll
            for (int nt = 0; nt < 8; nt++) {
                int rb = (wn + nt * 8 + grp) * PITCHW + ks * 8 + tig;
                bhi[nt][0] = sBhi[rb];
                bhi[nt][1] = sBhi[rb + 4];
                blo[nt][0] = sBlo[rb];
                blo[nt][1] = sBlo[rb + 4];
            }
#pragma unroll
            for (int mt = 0; mt < 2; mt++)
#pragma unroll
                for (int nt = 0; nt < 8; nt++) {
                    mma_bf16(c[mt][nt], ahi[mt], bhi[nt]);
                    mma_bf16(c[mt][nt], ahi[mt], blo[nt]);
                    mma_bf16(c[mt][nt], alo[mt], bhi[nt]);
                }
        }
        __syncthreads();
    }

    // epilogue
#pragma unroll
    for (int mt = 0; mt < 2; mt++) {
        int row = m0 + wm + mt * 16 + grp;
#pragma unroll
        for (int nt = 0; nt < 8; nt++) {
            int col = n0 + wn + nt * 8 + tig * 2;
            size_t i0 = (size_t)row * N + col;
            size_t i1 = (size_t)(row + 8) * N + col;
            float2 v0 = make_float2(c[mt][nt][0], c[mt][nt][1]);
            float2 v1 = make_float2(c[mt][nt][2], c[mt][nt][3]);
            if (addend) {
                float2 a0 = *(const float2*)(addend + i0);
                float2 a1 = *(const float2*)(addend + i1);
                v0.x += a0.x; v0.y += a0.y;
                v1.x += a1.x; v1.y += a1.y;
            }
            *(float2*)(C + i0) = v0;
            *(float2*)(C + i1) = v1;
        }
    }
}

// ---------------------------------------------------------------------------
// Embedding gather
// ---------------------------------------------------------------------------
__global__ void embed_kernel(const int* __restrict__ ids,
                             const float* __restrict__ embed,
                             float* __restrict__ res) {
    int t = blockIdx.x;
    int id = ids[t];
    const float4* src = (const float4*)(embed + (size_t)id * Hc);
    float4* dst = (float4*)(res + (size_t)t * Hc);
    for (int i = threadIdx.x; i < Hc / 4; i += blockDim.x)
        dst[i] = src[i];
}

// ---------------------------------------------------------------------------
// Fused (optional residual add) + RMSNorm.
// Output: fp32 (if outf) and/or split bf16 hi/lo (if ohi).
// ---------------------------------------------------------------------------
__global__ void addnorm_kernel(float* __restrict__ res,
                               const float* __restrict__ add,
                               const float* __restrict__ w,
                               float* __restrict__ outf,
                               __nv_bfloat16* __restrict__ ohi,
                               __nv_bfloat16* __restrict__ olo) {
    int t = blockIdx.x;
    int tid = threadIdx.x;
    float* rp = res + (size_t)t * Hc;
    float vals[8];
    float ss = 0.f;
#pragma unroll
    for (int i = 0; i < 8; i++) {
        int idx = tid + i * 256;
        float v = rp[idx];
        if (add) { v += add[(size_t)t * Hc + idx]; rp[idx] = v; }
        vals[i] = v;
        ss += v * v;
    }
    __shared__ float warp_s[8];
#pragma unroll
    for (int off = 16; off > 0; off >>= 1)
        ss += __shfl_down_sync(0xffffffff, ss, off);
    if ((tid & 31) == 0) warp_s[tid >> 5] = ss;
    __syncthreads();
    if (tid < 8) {
        float v = warp_s[tid];
#pragma unroll
        for (int off = 4; off > 0; off >>= 1)
            v += __shfl_down_sync(0xff, v, off);
        if (tid == 0) warp_s[0] = v;
    }
    __syncthreads();
    float inv = rsqrtf(warp_s[0] * (1.0f / Hc) + EPSc);
#pragma unroll
    for (int i = 0; i < 8; i++) {
        int idx = tid + i * 256;
        float o = vals[i] * inv * w[idx];
        if (outf) outf[(size_t)t * Hc + idx] = o;
        if (ohi) {
            __nv_bfloat16 h, l;
            split2(o, h, l);
            ohi[(size_t)t * Hc + idx] = h;
            olo[(size_t)t * Hc + idx] = l;
        }
    }
}

// ---------------------------------------------------------------------------
// RoPE + KV scatter (fp32, in-place on qkv)
// ---------------------------------------------------------------------------
__global__ void rope_kernel(float* __restrict__ qkv,
                            const int* __restrict__ pos,
                            float* __restrict__ kc,
                            float* __restrict__ vc) {
    int t = blockIdx.x;
    int b = t / Sc, s = t % Sc;
    int tid = threadIdx.x;
    float p = (float)pos[s];
    const float lt = logf(10000.f) / 32.f;

    for (int w = tid; w < (NHc + NKVc) * 32; w += blockDim.x) {
        int head = w / 32, j = w % 32;
        float ang = p * __expf(-(float)j * lt);
        float c = cosf(ang), sn = sinf(ang);
        if (head < NHc) {
            float* base = qkv + (size_t)t * QKVN + head * HDc;
            float x1 = base[j], x2 = base[j + 32];
            base[j]      = x1 * c - x2 * sn;
            base[j + 32] = x2 * c + x1 * sn;
        } else {
            int hk = head - NHc;
            const float* base = qkv + (size_t)t * QKVN + NHc * HDc + hk * HDc;
            float x1 = base[j], x2 = base[j + 32];
            float* kb = kc + (((size_t)(b * NKVc + hk)) * Sc + s) * HDc;
            kb[j]      = x1 * c - x2 * sn;
            kb[j + 32] = x2 * c + x1 * sn;
        }
    }
    for (int w = tid; w < NKVc * HDc; w += blockDim.x) {
        int hv = w / HDc, d = w % HDc;
        vc[(((size_t)(b * NKVc + hv)) * Sc + s) * HDc + d] =
            qkv[(size_t)t * QKVN + (NHc + NKVc) * HDc + hv * HDc + d];
    }
}

// ---------------------------------------------------------------------------
// Flash attention (causal, fp32). One block = 64 queries of one (b, head).
// Output split to bf16 hi/lo (feeds o-proj GEMM).
// ---------------------------------------------------------------------------
#define FPAD 68
struct __align__(16) FlashSmem {
    float Qs[64][FPAD];
    float Ks[64][FPAD];
    float Vs[64][FPAD];
    float Ss[64][FPAD];
    float mrow[64];
    float lrow[64];
    float arow[64];
};

__global__ void __launch_bounds__(256)
flash_kernel(const float* __restrict__ qbuf,
             const float* __restrict__ kc,
             const float* __restrict__ vc,
             __nv_bfloat16* __restrict__ ahi,
             __nv_bfloat16* __restrict__ alo) {
    extern __shared__ char smem_raw[];
    FlashSmem& sm = *reinterpret_cast<FlashSmem*>(smem_raw);

    int qb = blockIdx.x;
    int h  = blockIdx.y;
    int b  = blockIdx.z;
    int hkv = h / (NHc / NKVc);
    int tid = threadIdx.x;
    int ty = tid / 16, tx = tid % 16;
    const float scale = 0.125f;

#pragma unroll
    for (int rr = 0; rr < 4; rr++) {
        int row = (tid / 16) + rr * 16;
        int col = (tid % 16) * 4;
        const float* src = qbuf + ((size_t)(b * Sc + qb * 64 + row)) * QKVN + h * HDc + col;
        float4 v = *(const float4*)src;
        sm.Qs[col + 0][row] = v.x * scale;
        sm.Qs[col + 1][row] = v.y * scale;
        sm.Qs[col + 2][row] = v.z * scale;
        sm.Qs[col + 3][row] = v.w * scale;
    }
    if (tid < 64) { sm.mrow[tid] = -1e30f; sm.lrow[tid] = 0.f; }

    float oacc[4][4];
#pragma unroll
    for (int i = 0; i < 4; i++)
#pragma unroll
        for (int j = 0; j < 4; j++) oacc[i][j] = 0.f;

    __syncthreads();

    for (int kb = 0; kb <= qb; kb++) {
#pragma unroll
        for (int rr = 0; rr < 4; rr++) {
            int row = (tid / 16) + rr * 16;
            int col = (tid % 16) * 4;
            size_t kvbase = (((size_t)(b * NKVc + hkv)) * Sc + kb * 64 + row) * HDc + col;
            float4 k4 = *(const float4*)(kc + kvbase);
            sm.Ks[col + 0][row] = k4.x;
            sm.Ks[col + 1][row] = k4.y;
            sm.Ks[col + 2][row] = k4.z;
            sm.Ks[col + 3][row] = k4.w;
            *(float4*)&sm.Vs[row][col] = *(const float4*)(vc + kvbase);
        }
        __syncthreads();

        float sacc[4][4];
#pragma unroll
        for (int i = 0; i < 4; i++)
#pragma unroll
            for (int j = 0; j < 4; j++) sacc[i][j] = 0.f;
#pragma unroll 8
        for (int d = 0; d < 64; d++) {
            float qf[4], kf[4];
            *(float4*)qf = *(const float4*)&sm.Qs[d][ty * 4];
            *(float4*)kf = *(const float4*)&sm.Ks[d][tx * 4];
#pragma unroll
            for (int i = 0; i < 4; i++)
#pragma unroll
                for (int j = 0; j < 4; j++)
                    sacc[i][j] = fmaf(qf[i], kf[j], sacc[i][j]);
        }
        if (kb == qb) {
#pragma unroll
            for (int i = 0; i < 4; i++)
#pragma unroll
                for (int j = 0; j < 4; j++)
                    if (tx * 4 + j > ty * 4 + i) sacc[i][j] = -1e30f;
        }
#pragma unroll
        for (int i = 0; i < 4; i++)
#pragma unroll
            for (int j = 0; j < 4; j++)
                sm.Ss[tx * 4 + j][ty * 4 + i] = sacc[i][j];
        __syncthreads();

        if (tid < 64) {
            int q = tid;
            float m_old = sm.mrow[q];
            float m = m_old;
#pragma unroll 8
            for (int k = 0; k < 64; k++) m = fmaxf(m, sm.Ss[k][q]);
            float alpha = __expf(m_old - m);
            float ls = 0.f;
#pragma unroll 8
            for (int k = 0; k < 64; k++) {
                float pv = __expf(sm.Ss[k][q] - m);
                sm.Ss[k][q] = pv;
                ls += pv;
            }
            sm.mrow[q] = m;
            sm.lrow[q] = sm.lrow[q] * alpha + ls;
            sm.arow[q] = alpha;
        }
        __syncthreads();

        float al[4];
#pragma unroll
        for (int i = 0; i < 4; i++) al[i] = sm.arow[ty * 4 + i];
#pragma unroll
        for (int i = 0; i < 4; i++)
#pragma unroll
            for (int j = 0; j < 4; j++) oacc[i][j] *= al[i];
#pragma unroll 8
        for (int k = 0; k < 64; k++) {
            float pf[4], vf[4];
            *(float4*)pf = *(const float4*)&sm.Ss[k][ty * 4];
            *(float4*)vf = *(const float4*)&sm.Vs[k][tx * 4];
#pragma unroll
            for (int i = 0; i < 4; i++)
#pragma unroll
                for (int j = 0; j < 4; j++)
                    oacc[i][j] = fmaf(pf[i], vf[j], oacc[i][j]);
        }
        __syncthreads();
    }

#pragma unroll
    for (int i = 0; i < 4; i++) {
        float inv = 1.0f / sm.lrow[ty * 4 + i];
        int q = qb * 64 + ty * 4 + i;
        size_t base = ((size_t)(b * Sc + q)) * (NHc * HDc) + h * HDc + tx * 4;
#pragma unroll
        for (int j = 0; j < 4; j++) {
            float v = oacc[i][j] * inv;
            __nv_bfloat16 hbit, lbit;
            split2(v, hbit, lbit);
            ahi[base + j] = hbit;
            alo[base + j] = lbit;
        }
    }
}

// ---------------------------------------------------------------------------
// SwiGLU (output split bf16; feeds down GEMM)
// ---------------------------------------------------------------------------
__global__ void swiglu_kernel(const float* __restrict__ gu,
                              __nv_bfloat16* __restrict__ ahi,
                              __nv_bfloat16* __restrict__ alo) {
    size_t e = (size_t)blockIdx.x * blockDim.x + threadIdx.x;
    size_t t = e / Ic;
    size_t i = e % Ic;
    float g = gu[t * GUN + i];
    float u = gu[t * GUN + Ic + i];
    float sig = 1.0f / (1.0f + __expf(-g));
    float v = g * sig * u;
    __nv_bfloat16 h, l;
    split2(v, h, l);
    ahi[e] = h;
    alo[e] = l;
}

// ---------------------------------------------------------------------------
// Launch
// ---------------------------------------------------------------------------
extern "C" void kernel_launch(void* const* d_in, const int* in_sizes, int n_in,
                              void* d_out, int out_size) {
    const int*   input_ids = (const int*)d_in[0];
    const int*   positions = (const int*)d_in[1];
    const float* embed     = (const float*)d_in[2];
    const float* w_qkv     = (const float*)d_in[3];
    const float* w_o       = (const float*)d_in[4];
    const float* w_gate_up = (const float*)d_in[5];
    const float* w_down    = (const float*)d_in[6];
    const float* ln1_w     = (const float*)d_in[7];
    const float* ln2_w     = (const float*)d_in[8];
    const float* norm_w    = (const float*)d_in[9];
    float* out = (float*)d_out;

    float *res, *qkv, *kc, *vc, *gu, *hbuf;
    __nv_bfloat16 *hnh, *hnl, *ath, *atl, *ach, *acl, *wth, *wtl;
    cudaGetSymbolAddress((void**)&res,  g_res);
    cudaGetSymbolAddress((void**)&qkv,  g_qkv);
    cudaGetSymbolAddress((void**)&kc,   g_kc);
    cudaGetSymbolAddress((void**)&vc,   g_vc);
    cudaGetSymbolAddress((void**)&gu,   g_gu);
    cudaGetSymbolAddress((void**)&hbuf, g_h);
    cudaGetSymbolAddress((void**)&hnh,  g_hn_hi);
    cudaGetSymbolAddress((void**)&hnl,  g_hn_lo);
    cudaGetSymbolAddress((void**)&ath,  g_at_hi);
    cudaGetSymbolAddress((void**)&atl,  g_at_lo);
    cudaGetSymbolAddress((void**)&ach,  g_ac_hi);
    cudaGetSymbolAddress((void**)&acl,  g_ac_lo);
    cudaGetSymbolAddress((void**)&wth,  g_wt_hi);
    cudaGetSymbolAddress((void**)&wtl,  g_wt_lo);

    int flash_smem = (int)sizeof(FlashSmem);
    cudaFuncSetAttribute(flash_kernel, cudaFuncAttributeMaxDynamicSharedMemorySize, flash_smem);
    cudaFuncSetAttribute(gemm_bf16x2, cudaFuncAttributeMaxDynamicSharedMemorySize, GEMM_SMEM);

    // one-time weight transposes + bf16x2 split
    for (int l = 0; l < Lc; l++) {
        __nv_bfloat16* wh = wth + (size_t)l * WT_PER_L;
        __nv_bfloat16* wl = wtl + (size_t)l * WT_PER_L;
        transpose_split<<<dim3(QKVN / 32, Hc / 32), dim3(32, 8)>>>(
            w_qkv + (size_t)l * Hc * QKVN, wh + WT_QKV_OFF, wl + WT_QKV_OFF, Hc, QKVN);
        transpose_split<<<dim3(Hc / 32, Hc / 32), dim3(32, 8)>>>(
            w_o + (size_t)l * Hc * Hc, wh + WT_O_OFF, wl + WT_O_OFF, Hc, Hc);
        transpose_split<<<dim3(GUN / 32, Hc / 32), dim3(32, 8)>>>(
            w_gate_up + (size_t)l * Hc * GUN, wh + WT_GU_OFF, wl + WT_GU_OFF, Hc, GUN);
        transpose_split<<<dim3(Hc / 32, Ic / 32), dim3(32, 8)>>>(
            w_down + (size_t)l * Ic * Hc, wh + WT_DN_OFF, wl + WT_DN_OFF, Ic, Hc);
    }

    embed_kernel<<<Tc, 256>>>(input_ids, embed, res);

    for (int l = 0; l < Lc; l++) {
        __nv_bfloat16* wh = wth + (size_t)l * WT_PER_L;
        __nv_bfloat16* wl = wtl + (size_t)l * WT_PER_L;

        addnorm_kernel<<<Tc, 256>>>(res, l == 0 ? nullptr : hbuf,
                                    ln1_w + (size_t)l * Hc, nullptr, hnh, hnl);

        gemm_bf16x2<<<dim3(Tc / 128, QKVN / 128), 256, GEMM_SMEM>>>(
            hnh, hnl, wh + WT_QKV_OFF, wl + WT_QKV_OFF, qkv, nullptr, Tc, QKVN, Hc);

        rope_kernel<<<Tc, 128>>>(qkv, positions, kc, vc);

        flash_kernel<<<dim3(Sc / 64, NHc, Bc), 256, flash_smem>>>(qkv, kc, vc, ath, atl);

        gemm_bf16x2<<<dim3(Tc / 128, Hc / 128), 256, GEMM_SMEM>>>(
            ath, atl, wh + WT_O_OFF, wl + WT_O_OFF, res, res, Tc, Hc, Hc);

        addnorm_kernel<<<Tc, 256>>>(res, nullptr, ln2_w + (size_t)l * Hc, nullptr, hnh, hnl);

        gemm_bf16x2<<<dim3(Tc / 128, GUN / 128), 256, GEMM_SMEM>>>(
            hnh, hnl, wh + WT_GU_OFF, wl + WT_GU_OFF, gu, nullptr, Tc, GUN, Hc);

        swiglu_kernel<<<(Tc * (size_t)Ic) / 256, 256>>>(gu, ach, acl);

        gemm_bf16x2<<<dim3(Tc / 128, Hc / 128), 256, GEMM_SMEM>>>(
            ach, acl, wh + WT_DN_OFF, wl + WT_DN_OFF, hbuf, nullptr, Tc, Hc, Ic);
    }

    addnorm_kernel<<<Tc, 256>>>(res, hbuf, norm_w, out, nullptr, nullptr);
}

// round 5
// speedup vs baseline: 2.2437x; 1.0650x over previous
#include <cuda_runtime.h>
#include <cuda_bf16.h>
#include <math.h>
#include <stdint.h>

// ---------------------------------------------------------------------------
// Model constants
// ---------------------------------------------------------------------------
#define Lc 2
#define Hc 2048
#define NHc 32
#define NKVc 4
#define HDc 64
#define Ic 5632
#define Bc 2
#define Sc 1024
#define Tc (Bc * Sc)                   // 2048 tokens
#define QKVN ((NHc + 2 * NKVc) * HDc)  // 2560
#define GUN (2 * Ic)                   // 11264
#define EPSc 1e-5f

// ---------------------------------------------------------------------------
// Scratch (static device globals; no allocation allowed)
// ---------------------------------------------------------------------------
__device__ float g_res [Tc * Hc];
__device__ float g_qkv [Tc * QKVN];
__device__ float g_kc  [Bc * NKVc * Sc * HDc];
__device__ float g_vc  [Bc * NKVc * Sc * HDc];
__device__ float g_gu  [(size_t)Tc * GUN];
__device__ float g_h   [Tc * Hc];

// split activations (GEMM A operands)
__device__ __nv_bfloat16 g_hn_hi [Tc * Hc];
__device__ __nv_bfloat16 g_hn_lo [Tc * Hc];
__device__ __nv_bfloat16 g_at_hi [Tc * Hc];
__device__ __nv_bfloat16 g_at_lo [Tc * Hc];
__device__ __nv_bfloat16 g_ac_hi [(size_t)Tc * Ic];
__device__ __nv_bfloat16 g_ac_lo [(size_t)Tc * Ic];

// Transposed split weights: per layer [qkv_t(QKVN,H) | o_t(H,H) | gu_t(GUN,H) | down_t(H,I)]
#define WT_QKV_OFF 0
#define WT_O_OFF   ((size_t)QKVN * Hc)
#define WT_GU_OFF  (WT_O_OFF + (size_t)Hc * Hc)
#define WT_DN_OFF  (WT_GU_OFF + (size_t)GUN * Hc)
#define WT_PER_L   (WT_DN_OFF + (size_t)Hc * Ic)
__device__ __nv_bfloat16 g_wt_hi[2 * WT_PER_L];
__device__ __nv_bfloat16 g_wt_lo[2 * WT_PER_L];

// ---------------------------------------------------------------------------
// Helpers
// ---------------------------------------------------------------------------
__device__ __forceinline__ void split2(float x, __nv_bfloat16& hi, __nv_bfloat16& lo) {
    hi = __float2bfloat16(x);
    lo = __float2bfloat16(x - __bfloat162float(hi));
}

__device__ __forceinline__ uint32_t smem_u32(const void* p) {
    uint32_t a;
    asm("{ .reg .u64 t; cvta.to.shared.u64 t, %1; cvt.u32.u64 %0, t; }"
        : "=r"(a) : "l"(p));
    return a;
}

__device__ __forceinline__ void cp_async16(uint32_t smem_addr, const void* gptr) {
    asm volatile("cp.async.cg.shared.global [%0], [%1], 16;"
                 :: "r"(smem_addr), "l"(gptr) : "memory");
}
#define CP_COMMIT() asm volatile("cp.async.commit_group;" ::: "memory")
#define CP_WAIT0()  asm volatile("cp.async.wait_group 0;" ::: "memory")

__device__ __forceinline__ void mma_bf16(float* d, const uint32_t* a, const uint32_t* b) {
    asm volatile(
        "mma.sync.aligned.m16n8k16.row.col.f32.bf16.bf16.f32 "
        "{%0,%1,%2,%3}, {%4,%5,%6,%7}, {%8,%9}, {%0,%1,%2,%3};"
        : "+f"(d[0]), "+f"(d[1]), "+f"(d[2]), "+f"(d[3])
        : "r"(a[0]), "r"(a[1]), "r"(a[2]), "r"(a[3]),
          "r"(b[0]), "r"(b[1]));
}

// ---------------------------------------------------------------------------
// Weight transpose + bf16x2 split: src[K,N] -> hi/lo[N,K]
// ---------------------------------------------------------------------------
__global__ void transpose_split(const float* __restrict__ src,
                                __nv_bfloat16* __restrict__ hi,
                                __nv_bfloat16* __restrict__ lo,
                                int K, int N) {
    __shared__ float tile[32][33];
    int nb = blockIdx.x * 32;
    int kb = blockIdx.y * 32;
#pragma unroll
    for (int i = threadIdx.y; i < 32; i += 8)
        tile[i][threadIdx.x] = src[(size_t)(kb + i) * N + nb + threadIdx.x];
    __syncthreads();
#pragma unroll
    for (int i = threadIdx.y; i < 32; i += 8) {
        float v = tile[threadIdx.x][i];
        __nv_bfloat16 h, l;
        split2(v, h, l);
        size_t idx = (size_t)(nb + i) * K + kb + threadIdx.x;
        hi[idx] = h;
        lo[idx] = l;
    }
}

// ---------------------------------------------------------------------------
// bf16x2 split GEMM: C[M,N] = A[M,K] @ Bt[N,K]^T (+ addend)
// 3 terms: Ahi*Bhi + Ahi*Blo + Alo*Bhi (fp32 accum), term-major issue order
// so accumulator reuse distance is 8 independent MMAs.
// Block 128x128, BK=32, 256 threads (8 warps, 32x64 each), 2 CTAs/SM.
// ---------------------------------------------------------------------------
#define PITCHB 80                 // bytes per smem row (32 bf16 = 64B + 16B pad)
#define PITCHW 20                 // words per smem row
#define ABYTES (128 * PITCHB)     // 10240 per operand array
#define BUFB   (4 * ABYTES)       // 40960 per buffer
#define GEMM_SMEM (2 * BUFB)      // 81920

__global__ void __launch_bounds__(256, 2)
gemm_bf16x2(const __nv_bfloat16* __restrict__ Ahi,
            const __nv_bfloat16* __restrict__ Alo,
            const __nv_bfloat16* __restrict__ Bhi,
            const __nv_bfloat16* __restrict__ Blo,
            float* __restrict__ C, const float* __restrict__ addend,
            int M, int N, int K) {
    extern __shared__ char smraw[];
    uint32_t sbase = smem_u32(smraw);
    const uint32_t* smw = (const uint32_t*)smraw;

    const int tid  = threadIdx.x;
    const int warp = tid >> 5;
    const int lane = tid & 31;
    const int wm   = (warp >> 1) * 32;   // warp M offset (0,32,64,96)
    const int wn   = (warp & 1) * 64;    // warp N offset (0,64)
    const int grp  = lane >> 2;          // 0..7
    const int tig  = lane & 3;           // 0..3

    const int m0 = blockIdx.x * 128;
    const int n0 = blockIdx.y * 128;

    // staging: each thread owns 2 chunks of 16B per operand array
    const int r0 = tid >> 2;            // 0..63
    const int cc = tid & 3;             // 16B chunk within row
    const size_t gA0 = (size_t)(m0 + r0) * K + cc * 8;
    const size_t gA1 = gA0 + (size_t)64 * K;
    const size_t gB0 = (size_t)(n0 + r0) * K + cc * 8;
    const size_t gB1 = gB0 + (size_t)64 * K;
    const uint32_t s0 = (uint32_t)r0 * PITCHB + cc * 16;
    const uint32_t s1 = s0 + 64 * PITCHB;

    const int nkt = K >> 5;

    float c[2][8][4];
#pragma unroll
    for (int mt = 0; mt < 2; mt++)
#pragma unroll
        for (int nt = 0; nt < 8; nt++)
#pragma unroll
            for (int i = 0; i < 4; i++) c[mt][nt][i] = 0.f;

    // prologue: stage tile 0 into buffer 0
    {
        uint32_t b = sbase;
        cp_async16(b + s0,              Ahi + gA0);
        cp_async16(b + s1,              Ahi + gA1);
        cp_async16(b + ABYTES + s0,     Alo + gA0);
        cp_async16(b + ABYTES + s1,     Alo + gA1);
        cp_async16(b + 2*ABYTES + s0,   Bhi + gB0);
        cp_async16(b + 2*ABYTES + s1,   Bhi + gB1);
        cp_async16(b + 3*ABYTES + s0,   Blo + gB0);
        cp_async16(b + 3*ABYTES + s1,   Blo + gB1);
        CP_COMMIT();
    }

    for (int kt = 0; kt < nkt; kt++) {
        CP_WAIT0();
        __syncthreads();

        if (kt + 1 < nkt) {
            uint32_t b = sbase + (uint32_t)((kt + 1) & 1) * BUFB;
            size_t ko = (size_t)(kt + 1) * 32;
            cp_async16(b + s0,              Ahi + gA0 + ko);
            cp_async16(b + s1,              Ahi + gA1 + ko);
            cp_async16(b + ABYTES + s0,     Alo + gA0 + ko);
            cp_async16(b + ABYTES + s1,     Alo + gA1 + ko);
            cp_async16(b + 2*ABYTES + s0,   Bhi + gB0 + ko);
            cp_async16(b + 2*ABYTES + s1,   Bhi + gB1 + ko);
            cp_async16(b + 3*ABYTES + s0,   Blo + gB0 + ko);
            cp_async16(b + 3*ABYTES + s1,   Blo + gB1 + ko);
            CP_COMMIT();
        }

        const uint32_t* sAhi = smw + (size_t)(kt & 1) * (BUFB / 4);
        const uint32_t* sAlo = sAhi + ABYTES / 4;
        const uint32_t* sBhi = sAlo + ABYTES / 4;
        const uint32_t* sBlo = sBhi + ABYTES / 4;

#pragma unroll
        for (int ks = 0; ks < 2; ks++) {
            uint32_t ahi[2][4], alo[2][4];
#pragma unroll
            for (int mt = 0; mt < 2; mt++) {
                int rb = (wm + mt * 16 + grp) * PITCHW + ks * 8 + tig;
                ahi[mt][0] = sAhi[rb];
                ahi[mt][1] = sAhi[rb + 8 * PITCHW];
                ahi[mt][2] = sAhi[rb + 4];
                ahi[mt][3] = sAhi[rb + 8 * PITCHW + 4];
                alo[mt][0] = sAlo[rb];
                alo[mt][1] = sAlo[rb + 8 * PITCHW];
                alo[mt][2] = sAlo[rb + 4];
                alo[mt][3] = sAlo[rb + 8 * PITCHW + 4];
            }
            // process N in two halves of 4 to cut live fragment registers;
            // within each half, term-major ordering => 8 independent MMAs
            // between accumulator reuses.
#pragma unroll
            for (int nh = 0; nh < 2; nh++) {
                uint32_t bhi[4][2], blo[4][2];
#pragma unroll
                for (int nt = 0; nt < 4; nt++) {
                    int rb = (wn + (nh * 4 + nt) * 8 + grp) * PITCHW + ks * 8 + tig;
                    bhi[nt][0] = sBhi[rb];
                    bhi[nt][1] = sBhi[rb + 4];
                    blo[nt][0] = sBlo[rb];
                    blo[nt][1] = sBlo[rb + 4];
                }
#pragma unroll
                for (int mt = 0; mt < 2; mt++)
#pragma unroll
                    for (int nt = 0; nt < 4; nt++)
                        mma_bf16(c[mt][nh * 4 + nt], ahi[mt], bhi[nt]);
#pragma unroll
                for (int mt = 0; mt < 2; mt++)
#pragma unroll
                    for (int nt = 0; nt < 4; nt++)
                        mma_bf16(c[mt][nh * 4 + nt], ahi[mt], blo[nt]);
#pragma unroll
                for (int mt = 0; mt < 2; mt++)
#pragma unroll
                    for (int nt = 0; nt < 4; nt++)
                        mma_bf16(c[mt][nh * 4 + nt], alo[mt], bhi[nt]);
            }
        }
        __syncthreads();
    }

    // epilogue
#pragma unroll
    for (int mt = 0; mt < 2; mt++) {
        int row = m0 + wm + mt * 16 + grp;
#pragma unroll
        for (int nt = 0; nt < 8; nt++) {
            int col = n0 + wn + nt * 8 + tig * 2;
            size_t i0 = (size_t)row * N + col;
            size_t i1 = (size_t)(row + 8) * N + col;
            float2 v0 = make_float2(c[mt][nt][0], c[mt][nt][1]);
            float2 v1 = make_float2(c[mt][nt][2], c[mt][nt][3]);
            if (addend) {
                float2 a0 = *(const float2*)(addend + i0);
                float2 a1 = *(const float2*)(addend + i1);
                v0.x += a0.x; v0.y += a0.y;
                v1.x += a1.x; v1.y += a1.y;
            }
            *(float2*)(C + i0) = v0;
            *(float2*)(C + i1) = v1;
        }
    }
}

// ---------------------------------------------------------------------------
// Embedding gather
// ---------------------------------------------------------------------------
__global__ void embed_kernel(const int* __restrict__ ids,
                             const float* __restrict__ embed,
                             float* __restrict__ res) {
    int t = blockIdx.x;
    int id = ids[t];
    const float4* src = (const float4*)(embed + (size_t)id * Hc);
    float4* dst = (float4*)(res + (size_t)t * Hc);
    for (int i = threadIdx.x; i < Hc / 4; i += blockDim.x)
        dst[i] = src[i];
}

// ---------------------------------------------------------------------------
// Fused (optional residual add) + RMSNorm.
// Output: fp32 (if outf) and/or split bf16 hi/lo (if ohi).
// ---------------------------------------------------------------------------
__global__ void addnorm_kernel(float* __restrict__ res,
                               const float* __restrict__ add,
                               const float* __restrict__ w,
                               float* __restrict__ outf,
                               __nv_bfloat16* __restrict__ ohi,
                               __nv_bfloat16* __restrict__ olo) {
    int t = blockIdx.x;
    int tid = threadIdx.x;
    float* rp = res + (size_t)t * Hc;
    float vals[8];
    float ss = 0.f;
#pragma unroll
    for (int i = 0; i < 8; i++) {
        int idx = tid + i * 256;
        float v = rp[idx];
        if (add) { v += add[(size_t)t * Hc + idx]; rp[idx] = v; }
        vals[i] = v;
        ss += v * v;
    }
    __shared__ float warp_s[8];
#pragma unroll
    for (int off = 16; off > 0; off >>= 1)
        ss += __shfl_down_sync(0xffffffff, ss, off);
    if ((tid & 31) == 0) warp_s[tid >> 5] = ss;
    __syncthreads();
    if (tid < 8) {
        float v = warp_s[tid];
#pragma unroll
        for (int off = 4; off > 0; off >>= 1)
            v += __shfl_down_sync(0xff, v, off);
        if (tid == 0) warp_s[0] = v;
    }
    __syncthreads();
    float inv = rsqrtf(warp_s[0] * (1.0f / Hc) + EPSc);
#pragma unroll
    for (int i = 0; i < 8; i++) {
        int idx = tid + i * 256;
        float o = vals[i] * inv * w[idx];
        if (outf) outf[(size_t)t * Hc + idx] = o;
        if (ohi) {
            __nv_bfloat16 h, l;
            split2(o, h, l);
            ohi[(size_t)t * Hc + idx] = h;
            olo[(size_t)t * Hc + idx] = l;
        }
    }
}

// ---------------------------------------------------------------------------
// RoPE + KV scatter (fp32, in-place on qkv)
// ---------------------------------------------------------------------------
__global__ void rope_kernel(float* __restrict__ qkv,
                            const int* __restrict__ pos,
                            float* __restrict__ kc,
                            float* __restrict__ vc) {
    int t = blockIdx.x;
    int b = t / Sc, s = t % Sc;
    int tid = threadIdx.x;
    float p = (float)pos[s];
    const float lt = logf(10000.f) / 32.f;

    for (int w = tid; w < (NHc + NKVc) * 32; w += blockDim.x) {
        int head = w / 32, j = w % 32;
        float ang = p * __expf(-(float)j * lt);
        float c = cosf(ang), sn = sinf(ang);
        if (head < NHc) {
            float* base = qkv + (size_t)t * QKVN + head * HDc;
            float x1 = base[j], x2 = base[j + 32];
            base[j]      = x1 * c - x2 * sn;
            base[j + 32] = x2 * c + x1 * sn;
        } else {
            int hk = head - NHc;
            const float* base = qkv + (size_t)t * QKVN + NHc * HDc + hk * HDc;
            float x1 = base[j], x2 = base[j + 32];
            float* kb = kc + (((size_t)(b * NKVc + hk)) * Sc + s) * HDc;
            kb[j]      = x1 * c - x2 * sn;
            kb[j + 32] = x2 * c + x1 * sn;
        }
    }
    for (int w = tid; w < NKVc * HDc; w += blockDim.x) {
        int hv = w / HDc, d = w % HDc;
        vc[(((size_t)(b * NKVc + hv)) * Sc + s) * HDc + d] =
            qkv[(size_t)t * QKVN + (NHc + NKVc) * HDc + hv * HDc + d];
    }
}

// ---------------------------------------------------------------------------
// Flash attention (causal, fp32). One block = 64 queries of one (b, head).
// Output split to bf16 hi/lo (feeds o-proj GEMM).
// ---------------------------------------------------------------------------
#define FPAD 68
struct __align__(16) FlashSmem {
    float Qs[64][FPAD];
    float Ks[64][FPAD];
    float Vs[64][FPAD];
    float Ss[64][FPAD];
    float mrow[64];
    float lrow[64];
    float arow[64];
};

__global__ void __launch_bounds__(256)
flash_kernel(const float* __restrict__ qbuf,
             const float* __restrict__ kc,
             const float* __restrict__ vc,
             __nv_bfloat16* __restrict__ ahi,
             __nv_bfloat16* __restrict__ alo) {
    extern __shared__ char smem_raw[];
    FlashSmem& sm = *reinterpret_cast<FlashSmem*>(smem_raw);

    int qb = blockIdx.x;
    int h  = blockIdx.y;
    int b  = blockIdx.z;
    int hkv = h / (NHc / NKVc);
    int tid = threadIdx.x;
    int ty = tid / 16, tx = tid % 16;
    const float scale = 0.125f;

#pragma unroll
    for (int rr = 0; rr < 4; rr++) {
        int row = (tid / 16) + rr * 16;
        int col = (tid % 16) * 4;
        const float* src = qbuf + ((size_t)(b * Sc + qb * 64 + row)) * QKVN + h * HDc + col;
        float4 v = *(const float4*)src;
        sm.Qs[col + 0][row] = v.x * scale;
        sm.Qs[col + 1][row] = v.y * scale;
        sm.Qs[col + 2][row] = v.z * scale;
        sm.Qs[col + 3][row] = v.w * scale;
    }
    if (tid < 64) { sm.mrow[tid] = -1e30f; sm.lrow[tid] = 0.f; }

    float oacc[4][4];
#pragma unroll
    for (int i = 0; i < 4; i++)
#pragma unroll
        for (int j = 0; j < 4; j++) oacc[i][j] = 0.f;

    __syncthreads();

    for (int kb = 0; kb <= qb; kb++) {
#pragma unroll
        for (int rr = 0; rr < 4; rr++) {
            int row = (tid / 16) + rr * 16;
            int col = (tid % 16) * 4;
            size_t kvbase = (((size_t)(b * NKVc + hkv)) * Sc + kb * 64 + row) * HDc + col;
            float4 k4 = *(const float4*)(kc + kvbase);
            sm.Ks[col + 0][row] = k4.x;
            sm.Ks[col + 1][row] = k4.y;
            sm.Ks[col + 2][row] = k4.z;
            sm.Ks[col + 3][row] = k4.w;
            *(float4*)&sm.Vs[row][col] = *(const float4*)(vc + kvbase);
        }
        __syncthreads();

        float sacc[4][4];
#pragma unroll
        for (int i = 0; i < 4; i++)
#pragma unroll
            for (int j = 0; j < 4; j++) sacc[i][j] = 0.f;
#pragma unroll 8
        for (int d = 0; d < 64; d++) {
            float qf[4], kf[4];
            *(float4*)qf = *(const float4*)&sm.Qs[d][ty * 4];
            *(float4*)kf = *(const float4*)&sm.Ks[d][tx * 4];
#pragma unroll
            for (int i = 0; i < 4; i++)
#pragma unroll
                for (int j = 0; j < 4; j++)
                    sacc[i][j] = fmaf(qf[i], kf[j], sacc[i][j]);
        }
        if (kb == qb) {
#pragma unroll
            for (int i = 0; i < 4; i++)
#pragma unroll
                for (int j = 0; j < 4; j++)
                    if (tx * 4 + j > ty * 4 + i) sacc[i][j] = -1e30f;
        }
#pragma unroll
        for (int i = 0; i < 4; i++)
#pragma unroll
            for (int j = 0; j < 4; j++)
                sm.Ss[tx * 4 + j][ty * 4 + i] = sacc[i][j];
        __syncthreads();

        if (tid < 64) {
            int q = tid;
            float m_old = sm.mrow[q];
            float m = m_old;
#pragma unroll 8
            for (int k = 0; k < 64; k++) m = fmaxf(m, sm.Ss[k][q]);
            float alpha = __expf(m_old - m);
            float ls = 0.f;
#pragma unroll 8
            for (int k = 0; k < 64; k++) {
                float pv = __expf(sm.Ss[k][q] - m);
                sm.Ss[k][q] = pv;
                ls += pv;
            }
            sm.mrow[q] = m;
            sm.lrow[q] = sm.lrow[q] * alpha + ls;
            sm.arow[q] = alpha;
        }
        __syncthreads();

        float al[4];
#pragma unroll
        for (int i = 0; i < 4; i++) al[i] = sm.arow[ty * 4 + i];
#pragma unroll
        for (int i = 0; i < 4; i++)
#pragma unroll
            for (int j = 0; j < 4; j++) oacc[i][j] *= al[i];
#pragma unroll 8
        for (int k = 0; k < 64; k++) {
            float pf[4], vf[4];
            *(float4*)pf = *(const float4*)&sm.Ss[k][ty * 4];
            *(float4*)vf = *(const float4*)&sm.Vs[k][tx * 4];
#pragma unroll
            for (int i = 0; i < 4; i++)
#pragma unroll
                for (int j = 0; j < 4; j++)
                    oacc[i][j] = fmaf(pf[i], vf[j], oacc[i][j]);
        }
        __syncthreads();
    }

#pragma unroll
    for (int i = 0; i < 4; i++) {
        float inv = 1.0f / sm.lrow[ty * 4 + i];
        int q = qb * 64 + ty * 4 + i;
        size_t base = ((size_t)(b * Sc + q)) * (NHc * HDc) + h * HDc + tx * 4;
#pragma unroll
        for (int j = 0; j < 4; j++) {
            float v = oacc[i][j] * inv;
            __nv_bfloat16 hbit, lbit;
            split2(v, hbit, lbit);
            ahi[base + j] = hbit;
            alo[base + j] = lbit;
        }
    }
}

// ---------------------------------------------------------------------------
// SwiGLU (output split bf16; feeds down GEMM)
// ---------------------------------------------------------------------------
__global__ void swiglu_kernel(const float* __restrict__ gu,
                              __nv_bfloat16* __restrict__ ahi,
                              __nv_bfloat16* __restrict__ alo) {
    size_t e = (size_t)blockIdx.x * blockDim.x + threadIdx.x;
    size_t t = e / Ic;
    size_t i = e % Ic;
    float g = gu[t * GUN + i];
    float u = gu[t * GUN + Ic + i];
    float sig = 1.0f / (1.0f + __expf(-g));
    float v = g * sig * u;
    __nv_bfloat16 h, l;
    split2(v, h, l);
    ahi[e] = h;
    alo[e] = l;
}

// ---------------------------------------------------------------------------
// Launch
// ---------------------------------------------------------------------------
extern "C" void kernel_launch(void* const* d_in, const int* in_sizes, int n_in,
                              void* d_out, int out_size) {
    const int*   input_ids = (const int*)d_in[0];
    const int*   positions = (const int*)d_in[1];
    const float* embed     = (const float*)d_in[2];
    const float* w_qkv     = (const float*)d_in[3];
    const float* w_o       = (const float*)d_in[4];
    const float* w_gate_up = (const float*)d_in[5];
    const float* w_down    = (const float*)d_in[6];
    const float* ln1_w     = (const float*)d_in[7];
    const float* ln2_w     = (const float*)d_in[8];
    const float* norm_w    = (const float*)d_in[9];
    float* out = (float*)d_out;

    float *res, *qkv, *kc, *vc, *gu, *hbuf;
    __nv_bfloat16 *hnh, *hnl, *ath, *atl, *ach, *acl, *wth, *wtl;
    cudaGetSymbolAddress((void**)&res,  g_res);
    cudaGetSymbolAddress((void**)&qkv,  g_qkv);
    cudaGetSymbolAddress((void**)&kc,   g_kc);
    cudaGetSymbolAddress((void**)&vc,   g_vc);
    cudaGetSymbolAddress((void**)&gu,   g_gu);
    cudaGetSymbolAddress((void**)&hbuf, g_h);
    cudaGetSymbolAddress((void**)&hnh,  g_hn_hi);
    cudaGetSymbolAddress((void**)&hnl,  g_hn_lo);
    cudaGetSymbolAddress((void**)&ath,  g_at_hi);
    cudaGetSymbolAddress((void**)&atl,  g_at_lo);
    cudaGetSymbolAddress((void**)&ach,  g_ac_hi);
    cudaGetSymbolAddress((void**)&acl,  g_ac_lo);
    cudaGetSymbolAddress((void**)&wth,  g_wt_hi);
    cudaGetSymbolAddress((void**)&wtl,  g_wt_lo);

    int flash_smem = (int)sizeof(FlashSmem);
    cudaFuncSetAttribute(flash_kernel, cudaFuncAttributeMaxDynamicSharedMemorySize, flash_smem);
    cudaFuncSetAttribute(gemm_bf16x2, cudaFuncAttributeMaxDynamicSharedMemorySize, GEMM_SMEM);

    // one-time weight transposes + bf16x2 split
    for (int l = 0; l < Lc; l++) {
        __nv_bfloat16* wh = wth + (size_t)l * WT_PER_L;
        __nv_bfloat16* wl = wtl + (size_t)l * WT_PER_L;
        transpose_split<<<dim3(QKVN / 32, Hc / 32), dim3(32, 8)>>>(
            w_qkv + (size_t)l * Hc * QKVN, wh + WT_QKV_OFF, wl + WT_QKV_OFF, Hc, QKVN);
        transpose_split<<<dim3(Hc / 32, Hc / 32), dim3(32, 8)>>>(
            w_o + (size_t)l * Hc * Hc, wh + WT_O_OFF, wl + WT_O_OFF, Hc, Hc);
        transpose_split<<<dim3(GUN / 32, Hc / 32), dim3(32, 8)>>>(
            w_gate_up + (size_t)l * Hc * GUN, wh + WT_GU_OFF, wl + WT_GU_OFF, Hc, GUN);
        transpose_split<<<dim3(Hc / 32, Ic / 32), dim3(32, 8)>>>(
            w_down + (size_t)l * Ic * Hc, wh + WT_DN_OFF, wl + WT_DN_OFF, Ic, Hc);
    }

    embed_kernel<<<Tc, 256>>>(input_ids, embed, res);

    for (int l = 0; l < Lc; l++) {
        __nv_bfloat16* wh = wth + (size_t)l * WT_PER_L;
        __nv_bfloat16* wl = wtl + (size_t)l * WT_PER_L;

        addnorm_kernel<<<Tc, 256>>>(res, l == 0 ? nullptr : hbuf,
                                    ln1_w + (size_t)l * Hc, nullptr, hnh, hnl);

        gemm_bf16x2<<<dim3(Tc / 128, QKVN / 128), 256, GEMM_SMEM>>>(
            hnh, hnl, wh + WT_QKV_OFF, wl + WT_QKV_OFF, qkv, nullptr, Tc, QKVN, Hc);

        rope_kernel<<<Tc, 128>>>(qkv, positions, kc, vc);

        flash_kernel<<<dim3(Sc / 64, NHc, Bc), 256, flash_smem>>>(qkv, kc, vc, ath, atl);

        gemm_bf16x2<<<dim3(Tc / 128, Hc / 128), 256, GEMM_SMEM>>>(
            ath, atl, wh + WT_O_OFF, wl + WT_O_OFF, res, res, Tc, Hc, Hc);

        addnorm_kernel<<<Tc, 256>>>(res, nullptr, ln2_w + (size_t)l * Hc, nullptr, hnh, hnl);

        gemm_bf16x2<<<dim3(Tc / 128, GUN / 128), 256, GEMM_SMEM>>>(
            hnh, hnl, wh + WT_GU_OFF, wl + WT_GU_OFF, gu, nullptr, Tc, GUN, Hc);

        swiglu_kernel<<<(Tc * (size_t)Ic) / 256, 256>>>(gu, ach, acl);

        gemm_bf16x2<<<dim3(Tc / 128, Hc / 128), 256, GEMM_SMEM>>>(
            ach, acl, wh + WT_DN_OFF, wl + WT_DN_OFF, hbuf, nullptr, Tc, Hc, Ic);
    }

    addnorm_kernel<<<Tc, 256>>>(res, hbuf, norm_w, out, nullptr, nullptr);
}

// round 6
// speedup vs baseline: 2.4211x; 1.0790x over previous
#include <cuda_runtime.h>
#include <cuda_bf16.h>
#include <math.h>
#include <stdint.h>

// ---------------------------------------------------------------------------
// Model constants
// ---------------------------------------------------------------------------
#define Lc 2
#define Hc 2048
#define NHc 32
#define NKVc 4
#define HDc 64
#define Ic 5632
#define Bc 2
#define Sc 1024
#define Tc (Bc * Sc)                   // 2048 tokens
#define QKVN ((NHc + 2 * NKVc) * HDc)  // 2560
#define GUN (2 * Ic)                   // 11264
#define EPSc 1e-5f

// ---------------------------------------------------------------------------
// Scratch (static device globals; no allocation allowed)
// ---------------------------------------------------------------------------
__device__ float g_res [Tc * Hc];
__device__ float g_qkv [Tc * QKVN];
__device__ float g_kc  [Bc * NKVc * Sc * HDc];
__device__ float g_vc  [Bc * NKVc * Sc * HDc];
__device__ float g_gu  [(size_t)Tc * GUN];
__device__ float g_h   [Tc * Hc];

// split activations (GEMM A operands)
__device__ __nv_bfloat16 g_hn_hi [Tc * Hc];
__device__ __nv_bfloat16 g_hn_lo [Tc * Hc];
__device__ __nv_bfloat16 g_at_hi [Tc * Hc];
__device__ __nv_bfloat16 g_at_lo [Tc * Hc];
__device__ __nv_bfloat16 g_ac_hi [(size_t)Tc * Ic];
__device__ __nv_bfloat16 g_ac_lo [(size_t)Tc * Ic];

// Transposed split weights: per layer [qkv_t(QKVN,H) | o_t(H,H) | gu_t(GUN,H) | down_t(H,I)]
#define WT_QKV_OFF 0
#define WT_O_OFF   ((size_t)QKVN * Hc)
#define WT_GU_OFF  (WT_O_OFF + (size_t)Hc * Hc)
#define WT_DN_OFF  (WT_GU_OFF + (size_t)GUN * Hc)
#define WT_PER_L   (WT_DN_OFF + (size_t)Hc * Ic)
__device__ __nv_bfloat16 g_wt_hi[2 * WT_PER_L];
__device__ __nv_bfloat16 g_wt_lo[2 * WT_PER_L];

// ---------------------------------------------------------------------------
// Helpers
// ---------------------------------------------------------------------------
__device__ __forceinline__ void split2(float x, __nv_bfloat16& hi, __nv_bfloat16& lo) {
    hi = __float2bfloat16(x);
    lo = __float2bfloat16(x - __bfloat162float(hi));
}

__device__ __forceinline__ uint32_t smem_u32(const void* p) {
    uint32_t a;
    asm("{ .reg .u64 t; cvta.to.shared.u64 t, %1; cvt.u32.u64 %0, t; }"
        : "=r"(a) : "l"(p));
    return a;
}

__device__ __forceinline__ void cp_async16(uint32_t smem_addr, const void* gptr) {
    asm volatile("cp.async.cg.shared.global [%0], [%1], 16;"
                 :: "r"(smem_addr), "l"(gptr) : "memory");
}
#define CP_COMMIT() asm volatile("cp.async.commit_group;" ::: "memory")
#define CP_WAIT2()  asm volatile("cp.async.wait_group 2;" ::: "memory")

__device__ __forceinline__ void mma_bf16(float* d, const uint32_t* a, const uint32_t* b) {
    asm volatile(
        "mma.sync.aligned.m16n8k16.row.col.f32.bf16.bf16.f32 "
        "{%0,%1,%2,%3}, {%4,%5,%6,%7}, {%8,%9}, {%0,%1,%2,%3};"
        : "+f"(d[0]), "+f"(d[1]), "+f"(d[2]), "+f"(d[3])
        : "r"(a[0]), "r"(a[1]), "r"(a[2]), "r"(a[3]),
          "r"(b[0]), "r"(b[1]));
}

#define LDSM4(R, A) \
    asm volatile("ldmatrix.sync.aligned.m8n8.x4.shared.b16 {%0,%1,%2,%3}, [%4];" \
        : "=r"((R)[0]), "=r"((R)[1]), "=r"((R)[2]), "=r"((R)[3]) : "r"(A))

// ---------------------------------------------------------------------------
// Fused weight prep: transpose + bf16x2 split for all 8 weight matrices.
// src[K,N] -> hi/lo[N,K]. Grid = 86016 blocks of (32,8).
// per-layer tiles: qkv 80x64=5120 | o 64x64=4096 | gu 352x64=22528 | dn 64x176=11264
// ---------------------------------------------------------------------------
#define TILES_PER_LAYER 43008
__global__ void prep_weights(const float* __restrict__ wqkv,
                             const float* __restrict__ wo,
                             const float* __restrict__ wgu,
                             const float* __restrict__ wdn,
                             __nv_bfloat16* __restrict__ wth,
                             __nv_bfloat16* __restrict__ wtl) {
    __shared__ float tile[32][33];
    int bid = blockIdx.x;
    int l = 0;
    if (bid >= TILES_PER_LAYER) { l = 1; bid -= TILES_PER_LAYER; }
    size_t loff = (size_t)l * WT_PER_L;

    const float* src;
    __nv_bfloat16 *hi, *lo;
    int K, N;
    if (bid < 5120) {
        src = wqkv + (size_t)l * Hc * QKVN;
        hi = wth + loff + WT_QKV_OFF; lo = wtl + loff + WT_QKV_OFF;
        K = Hc; N = QKVN;
    } else if (bid < 9216) {
        bid -= 5120;
        src = wo + (size_t)l * Hc * Hc;
        hi = wth + loff + WT_O_OFF; lo = wtl + loff + WT_O_OFF;
        K = Hc; N = Hc;
    } else if (bid < 31744) {
        bid -= 9216;
        src = wgu + (size_t)l * Hc * GUN;
        hi = wth + loff + WT_GU_OFF; lo = wtl + loff + WT_GU_OFF;
        K = Hc; N = GUN;
    } else {
        bid -= 31744;
        src = wdn + (size_t)l * Ic * Hc;
        hi = wth + loff + WT_DN_OFF; lo = wtl + loff + WT_DN_OFF;
        K = Ic; N = Hc;
    }
    int tilesX = N / 32;
    int nb = (bid % tilesX) * 32;
    int kb = (bid / tilesX) * 32;

#pragma unroll
    for (int i = threadIdx.y; i < 32; i += 8)
        tile[i][threadIdx.x] = src[(size_t)(kb + i) * N + nb + threadIdx.x];
    __syncthreads();
#pragma unroll
    for (int i = threadIdx.y; i < 32; i += 8) {
        float v = tile[threadIdx.x][i];
        __nv_bfloat16 h, lv;
        split2(v, h, lv);
        size_t idx = (size_t)(nb + i) * K + kb + threadIdx.x;
        hi[idx] = h;
        lo[idx] = lv;
    }
}

// ---------------------------------------------------------------------------
// bf16x2 split GEMM: C[M,N] = A[M,K] @ Bt[N,K]^T (+ addend)
// 3 terms hi*hi + hi*lo + lo*hi, fp32 accum, term-major ordering.
// Block 128x128, BK=16, 256 threads (8 warps, 32x64 warp tiles).
// 4-stage cp.async pipeline (wait_group 2), ldmatrix fragment loads.
// ---------------------------------------------------------------------------
#define RPITCH 48                   // bytes per smem row (16 bf16 = 32B + 16B pad)
#define ARRB   (128 * RPITCH)       // 6144 per operand array
#define STAGEB (4 * ARRB)           // 24576 per stage
#define GEMM_SMEM (4 * STAGEB)      // 98304 (4 stages)

__global__ void __launch_bounds__(256, 2)
gemm_bf16x2(const __nv_bfloat16* __restrict__ Ahi,
            const __nv_bfloat16* __restrict__ Alo,
            const __nv_bfloat16* __restrict__ Bhi,
            const __nv_bfloat16* __restrict__ Blo,
            float* __restrict__ C, const float* __restrict__ addend,
            int M, int N, int K) {
    extern __shared__ char smraw[];
    uint32_t sbase = smem_u32(smraw);

    const int tid  = threadIdx.x;
    const int warp = tid >> 5;
    const int lane = tid & 31;
    const int wm   = (warp >> 1) * 32;   // warp M offset
    const int wn   = (warp & 1) * 64;    // warp N offset
    const int grp  = lane >> 2;
    const int tig  = lane & 3;

    const int m0 = blockIdx.x * 128;
    const int n0 = blockIdx.y * 128;

    // ldmatrix lane offsets
    const int li = lane >> 3;            // matrix group 0..3
    const int lr = lane & 7;             // row within matrix
    const uint32_t aoffl = (uint32_t)(((li & 1) * 8 + lr) * RPITCH + (li >> 1) * 16);
    const uint32_t boffl = (uint32_t)(((li >> 1) * 8 + lr) * RPITCH + (li & 1) * 16);

    // cp.async staging: thread covers row r0, 16B half of each array
    const int r0   = tid >> 1;           // 0..127
    const int half = tid & 1;
    const uint32_t sdst = (uint32_t)(r0 * RPITCH + half * 16);
    const __nv_bfloat16* pAhi = Ahi + (size_t)(m0 + r0) * K + half * 8;
    const __nv_bfloat16* pAlo = Alo + (size_t)(m0 + r0) * K + half * 8;
    const __nv_bfloat16* pBhi = Bhi + (size_t)(n0 + r0) * K + half * 8;
    const __nv_bfloat16* pBlo = Blo + (size_t)(n0 + r0) * K + half * 8;

    const int nkt = K >> 4;

    float c[2][8][4];
#pragma unroll
    for (int mt = 0; mt < 2; mt++)
#pragma unroll
        for (int nt = 0; nt < 8; nt++)
#pragma unroll
            for (int i = 0; i < 4; i++) c[mt][nt][i] = 0.f;

    // prologue: stage tiles 0..2
#pragma unroll
    for (int s = 0; s < 3; s++) {
        uint32_t b = sbase + (uint32_t)s * STAGEB + sdst;
        int ko = s * 16;
        cp_async16(b,            pAhi + ko);
        cp_async16(b + ARRB,     pAlo + ko);
        cp_async16(b + 2 * ARRB, pBhi + ko);
        cp_async16(b + 3 * ARRB, pBlo + ko);
        CP_COMMIT();
    }

    for (int kt = 0; kt < nkt; kt++) {
        CP_WAIT2();            // tile kt's group complete (own thread)
        __syncthreads();       // all threads' loads of tile kt visible

        // ---- compute tile kt ----
        uint32_t sb = sbase + (uint32_t)(kt & 3) * STAGEB;

        uint32_t ahi[2][4], alo[2][4];
#pragma unroll
        for (int mt = 0; mt < 2; mt++) {
            uint32_t aaddr = sb + (uint32_t)((wm + mt * 16) * RPITCH) + aoffl;
            LDSM4(ahi[mt], aaddr);
            LDSM4(alo[mt], aaddr + ARRB);
        }
#pragma unroll
        for (int nh = 0; nh < 2; nh++) {
            uint32_t bhi[2][4], blo[2][4];
#pragma unroll
            for (int p = 0; p < 2; p++) {
                uint32_t baddr = sb + 2 * ARRB +
                                 (uint32_t)((wn + nh * 32 + p * 16) * RPITCH) + boffl;
                LDSM4(bhi[p], baddr);
                LDSM4(blo[p], baddr + ARRB);
            }
            // term-major: hi*hi, hi*lo, lo*hi (8 independent MMAs between reuses)
#pragma unroll
            for (int mt = 0; mt < 2; mt++)
#pragma unroll
                for (int p = 0; p < 2; p++)
#pragma unroll
                    for (int h = 0; h < 2; h++)
                        mma_bf16(c[mt][nh * 4 + p * 2 + h], ahi[mt], &bhi[p][h * 2]);
#pragma unroll
            for (int mt = 0; mt < 2; mt++)
#pragma unroll
                for (int p = 0; p < 2; p++)
#pragma unroll
                    for (int h = 0; h < 2; h++)
                        mma_bf16(c[mt][nh * 4 + p * 2 + h], ahi[mt], &blo[p][h * 2]);
#pragma unroll
            for (int mt = 0; mt < 2; mt++)
#pragma unroll
                for (int p = 0; p < 2; p++)
#pragma unroll
                    for (int h = 0; h < 2; h++)
                        mma_bf16(c[mt][nh * 4 + p * 2 + h], alo[mt], &bhi[p][h * 2]);
        }

        // ---- prefetch tile kt+3 into stage (kt+3)&3 (== stage of kt-1, safe
        // because every warp passed this iteration's barrier after computing kt-1)
        if (kt + 3 < nkt) {
            uint32_t b = sbase + (uint32_t)((kt + 3) & 3) * STAGEB + sdst;
            int ko = (kt + 3) * 16;
            cp_async16(b,            pAhi + ko);
            cp_async16(b + ARRB,     pAlo + ko);
            cp_async16(b + 2 * ARRB, pBhi + ko);
            cp_async16(b + 3 * ARRB, pBlo + ko);
        }
        CP_COMMIT();           // commit every iteration (possibly empty) to keep group count aligned
    }

    // epilogue
#pragma unroll
    for (int mt = 0; mt < 2; mt++) {
        int row = m0 + wm + mt * 16 + grp;
#pragma unroll
        for (int nt = 0; nt < 8; nt++) {
            int col = n0 + wn + nt * 8 + tig * 2;
            size_t i0 = (size_t)row * N + col;
            size_t i1 = (size_t)(row + 8) * N + col;
            float2 v0 = make_float2(c[mt][nt][0], c[mt][nt][1]);
            float2 v1 = make_float2(c[mt][nt][2], c[mt][nt][3]);
            if (addend) {
                float2 a0 = *(const float2*)(addend + i0);
                float2 a1 = *(const float2*)(addend + i1);
                v0.x += a0.x; v0.y += a0.y;
                v1.x += a1.x; v1.y += a1.y;
            }
            *(float2*)(C + i0) = v0;
            *(float2*)(C + i1) = v1;
        }
    }
}

// ---------------------------------------------------------------------------
// Embedding gather
// ---------------------------------------------------------------------------
__global__ void embed_kernel(const int* __restrict__ ids,
                             const float* __restrict__ embed,
                             float* __restrict__ res) {
    int t = blockIdx.x;
    int id = ids[t];
    const float4* src = (const float4*)(embed + (size_t)id * Hc);
    float4* dst = (float4*)(res + (size_t)t * Hc);
    for (int i = threadIdx.x; i < Hc / 4; i += blockDim.x)
        dst[i] = src[i];
}

// ---------------------------------------------------------------------------
// Fused (optional residual add) + RMSNorm.
// ---------------------------------------------------------------------------
__global__ void addnorm_kernel(float* __restrict__ res,
                               const float* __restrict__ add,
                               const float* __restrict__ w,
                               float* __restrict__ outf,
                               __nv_bfloat16* __restrict__ ohi,
                               __nv_bfloat16* __restrict__ olo) {
    int t = blockIdx.x;
    int tid = threadIdx.x;
    float* rp = res + (size_t)t * Hc;
    float vals[8];
    float ss = 0.f;
#pragma unroll
    for (int i = 0; i < 8; i++) {
        int idx = tid + i * 256;
        float v = rp[idx];
        if (add) { v += add[(size_t)t * Hc + idx]; rp[idx] = v; }
        vals[i] = v;
        ss += v * v;
    }
    __shared__ float warp_s[8];
#pragma unroll
    for (int off = 16; off > 0; off >>= 1)
        ss += __shfl_down_sync(0xffffffff, ss, off);
    if ((tid & 31) == 0) warp_s[tid >> 5] = ss;
    __syncthreads();
    if (tid < 8) {
        float v = warp_s[tid];
#pragma unroll
        for (int off = 4; off > 0; off >>= 1)
            v += __shfl_down_sync(0xff, v, off);
        if (tid == 0) warp_s[0] = v;
    }
    __syncthreads();
    float inv = rsqrtf(warp_s[0] * (1.0f / Hc) + EPSc);
#pragma unroll
    for (int i = 0; i < 8; i++) {
        int idx = tid + i * 256;
        float o = vals[i] * inv * w[idx];
        if (outf) outf[(size_t)t * Hc + idx] = o;
        if (ohi) {
            __nv_bfloat16 h, l;
            split2(o, h, l);
            ohi[(size_t)t * Hc + idx] = h;
            olo[(size_t)t * Hc + idx] = l;
        }
    }
}

// ---------------------------------------------------------------------------
// RoPE + KV scatter (fp32, in-place on qkv)
// ---------------------------------------------------------------------------
__global__ void rope_kernel(float* __restrict__ qkv,
                            const int* __restrict__ pos,
                            float* __restrict__ kc,
                            float* __restrict__ vc) {
    int t = blockIdx.x;
    int b = t / Sc, s = t % Sc;
    int tid = threadIdx.x;
    float p = (float)pos[s];
    const float lt = logf(10000.f) / 32.f;

    for (int w = tid; w < (NHc + NKVc) * 32; w += blockDim.x) {
        int head = w / 32, j = w % 32;
        float ang = p * __expf(-(float)j * lt);
        float c = cosf(ang), sn = sinf(ang);
        if (head < NHc) {
            float* base = qkv + (size_t)t * QKVN + head * HDc;
            float x1 = base[j], x2 = base[j + 32];
            base[j]      = x1 * c - x2 * sn;
            base[j + 32] = x2 * c + x1 * sn;
        } else {
            int hk = head - NHc;
            const float* base = qkv + (size_t)t * QKVN + NHc * HDc + hk * HDc;
            float x1 = base[j], x2 = base[j + 32];
            float* kb = kc + (((size_t)(b * NKVc + hk)) * Sc + s) * HDc;
            kb[j]      = x1 * c - x2 * sn;
            kb[j + 32] = x2 * c + x1 * sn;
        }
    }
    for (int w = tid; w < NKVc * HDc; w += blockDim.x) {
        int hv = w / HDc, d = w % HDc;
        vc[(((size_t)(b * NKVc + hv)) * Sc + s) * HDc + d] =
            qkv[(size_t)t * QKVN + (NHc + NKVc) * HDc + hv * HDc + d];
    }
}

// ---------------------------------------------------------------------------
// Flash attention (causal, fp32). One block = 64 queries of one (b, head).
// Softmax parallelized 4 threads/row. Output split to bf16 hi/lo.
// ---------------------------------------------------------------------------
#define FPAD 68
struct __align__(16) FlashSmem {
    float Qs[64][FPAD];
    float Ks[64][FPAD];
    float Vs[64][FPAD];
    float Ss[64][FPAD];
    float mrow[64];
    float lrow[64];
    float arow[64];
};

__global__ void __launch_bounds__(256)
flash_kernel(const float* __restrict__ qbuf,
             const float* __restrict__ kc,
             const float* __restrict__ vc,
             __nv_bfloat16* __restrict__ ahi,
             __nv_bfloat16* __restrict__ alo) {
    extern __shared__ char smem_raw[];
    FlashSmem& sm = *reinterpret_cast<FlashSmem*>(smem_raw);

    int qb = blockIdx.x;
    int h  = blockIdx.y;
    int b  = blockIdx.z;
    int hkv = h / (NHc / NKVc);
    int tid = threadIdx.x;
    int ty = tid / 16, tx = tid % 16;
    const float scale = 0.125f;

#pragma unroll
    for (int rr = 0; rr < 4; rr++) {
        int row = (tid / 16) + rr * 16;
        int col = (tid % 16) * 4;
        const float* src = qbuf + ((size_t)(b * Sc + qb * 64 + row)) * QKVN + h * HDc + col;
        float4 v = *(const float4*)src;
        sm.Qs[col + 0][row] = v.x * scale;
        sm.Qs[col + 1][row] = v.y * scale;
        sm.Qs[col + 2][row] = v.z * scale;
        sm.Qs[col + 3][row] = v.w * scale;
    }
    if (tid < 64) { sm.mrow[tid] = -1e30f; sm.lrow[tid] = 0.f; }

    float oacc[4][4];
#pragma unroll
    for (int i = 0; i < 4; i++)
#pragma unroll
        for (int j = 0; j < 4; j++) oacc[i][j] = 0.f;

    __syncthreads();

    for (int kb = 0; kb <= qb; kb++) {
#pragma unroll
        for (int rr = 0; rr < 4; rr++) {
            int row = (tid / 16) + rr * 16;
            int col = (tid % 16) * 4;
            size_t kvbase = (((size_t)(b * NKVc + hkv)) * Sc + kb * 64 + row) * HDc + col;
            float4 k4 = *(const float4*)(kc + kvbase);
            sm.Ks[col + 0][row] = k4.x;
            sm.Ks[col + 1][row] = k4.y;
            sm.Ks[col + 2][row] = k4.z;
            sm.Ks[col + 3][row] = k4.w;
            *(float4*)&sm.Vs[row][col] = *(const float4*)(vc + kvbase);
        }
        __syncthreads();

        float sacc[4][4];
#pragma unroll
        for (int i = 0; i < 4; i++)
#pragma unroll
            for (int j = 0; j < 4; j++) sacc[i][j] = 0.f;
#pragma unroll 8
        for (int d = 0; d < 64; d++) {
            float qf[4], kf[4];
            *(float4*)qf = *(const float4*)&sm.Qs[d][ty * 4];
            *(float4*)kf = *(const float4*)&sm.Ks[d][tx * 4];
#pragma unroll
            for (int i = 0; i < 4; i++)
#pragma unroll
                for (int j = 0; j < 4; j++)
                    sacc[i][j] = fmaf(qf[i], kf[j], sacc[i][j]);
        }
        if (kb == qb) {
#pragma unroll
            for (int i = 0; i < 4; i++)
#pragma unroll
                for (int j = 0; j < 4; j++)
                    if (tx * 4 + j > ty * 4 + i) sacc[i][j] = -1e30f;
        }
#pragma unroll
        for (int i = 0; i < 4; i++)
#pragma unroll
            for (int j = 0; j < 4; j++)
                sm.Ss[tx * 4 + j][ty * 4 + i] = sacc[i][j];
        __syncthreads();

        // ---- online softmax: 4 threads per query row ----
        {
            int q = tid >> 2;
            int part = tid & 3;
            float m_old = sm.mrow[q];
            float m = m_old;
#pragma unroll
            for (int i = 0; i < 16; i++)
                m = fmaxf(m, sm.Ss[part + i * 4][q]);
            m = fmaxf(m, __shfl_xor_sync(0xffffffffu, m, 1));
            m = fmaxf(m, __shfl_xor_sync(0xffffffffu, m, 2));
            float ls = 0.f;
#pragma unroll
            for (int i = 0; i < 16; i++) {
                int k = part + i * 4;
                float pv = __expf(sm.Ss[k][q] - m);
                sm.Ss[k][q] = pv;
                ls += pv;
            }
            ls += __shfl_xor_sync(0xffffffffu, ls, 1);
            ls += __shfl_xor_sync(0xffffffffu, ls, 2);
            if (part == 0) {
                float alpha = __expf(m_old - m);
                sm.mrow[q] = m;
                sm.lrow[q] = sm.lrow[q] * alpha + ls;
                sm.arow[q] = alpha;
            }
        }
        __syncthreads();

        float al[4];
#pragma unroll
        for (int i = 0; i < 4; i++) al[i] = sm.arow[ty * 4 + i];
#pragma unroll
        for (int i = 0; i < 4; i++)
#pragma unroll
            for (int j = 0; j < 4; j++) oacc[i][j] *= al[i];
#pragma unroll 8
        for (int k = 0; k < 64; k++) {
            float pf[4], vf[4];
            *(float4*)pf = *(const float4*)&sm.Ss[k][ty * 4];
            *(float4*)vf = *(const float4*)&sm.Vs[k][tx * 4];
#pragma unroll
            for (int i = 0; i < 4; i++)
#pragma unroll
                for (int j = 0; j < 4; j++)
                    oacc[i][j] = fmaf(pf[i], vf[j], oacc[i][j]);
        }
        __syncthreads();
    }

#pragma unroll
    for (int i = 0; i < 4; i++) {
        float inv = 1.0f / sm.lrow[ty * 4 + i];
        int q = qb * 64 + ty * 4 + i;
        size_t base = ((size_t)(b * Sc + q)) * (NHc * HDc) + h * HDc + tx * 4;
#pragma unroll
        for (int j = 0; j < 4; j++) {
            float v = oacc[i][j] * inv;
            __nv_bfloat16 hbit, lbit;
            split2(v, hbit, lbit);
            ahi[base + j] = hbit;
            alo[base + j] = lbit;
        }
    }
}

// ---------------------------------------------------------------------------
// SwiGLU (output split bf16; feeds down GEMM)
// ---------------------------------------------------------------------------
__global__ void swiglu_kernel(const float* __restrict__ gu,
                              __nv_bfloat16* __restrict__ ahi,
                              __nv_bfloat16* __restrict__ alo) {
    size_t e = (size_t)blockIdx.x * blockDim.x + threadIdx.x;
    size_t t = e / Ic;
    size_t i = e % Ic;
    float g = gu[t * GUN + i];
    float u = gu[t * GUN + Ic + i];
    float sig = 1.0f / (1.0f + __expf(-g));
    float v = g * sig * u;
    __nv_bfloat16 h, l;
    split2(v, h, l);
    ahi[e] = h;
    alo[e] = l;
}

// ---------------------------------------------------------------------------
// Launch
// ---------------------------------------------------------------------------
extern "C" void kernel_launch(void* const* d_in, const int* in_sizes, int n_in,
                              void* d_out, int out_size) {
    const int*   input_ids = (const int*)d_in[0];
    const int*   positions = (const int*)d_in[1];
    const float* embed     = (const float*)d_in[2];
    const float* w_qkv     = (const float*)d_in[3];
    const float* w_o       = (const float*)d_in[4];
    const float* w_gate_up = (const float*)d_in[5];
    const float* w_down    = (const float*)d_in[6];
    const float* ln1_w     = (const float*)d_in[7];
    const float* ln2_w     = (const float*)d_in[8];
    const float* norm_w    = (const float*)d_in[9];
    float* out = (float*)d_out;

    float *res, *qkv, *kc, *vc, *gu, *hbuf;
    __nv_bfloat16 *hnh, *hnl, *ath, *atl, *ach, *acl, *wth, *wtl;
    cudaGetSymbolAddress((void**)&res,  g_res);
    cudaGetSymbolAddress((void**)&qkv,  g_qkv);
    cudaGetSymbolAddress((void**)&kc,   g_kc);
    cudaGetSymbolAddress((void**)&vc,   g_vc);
    cudaGetSymbolAddress((void**)&gu,   g_gu);
    cudaGetSymbolAddress((void**)&hbuf, g_h);
    cudaGetSymbolAddress((void**)&hnh,  g_hn_hi);
    cudaGetSymbolAddress((void**)&hnl,  g_hn_lo);
    cudaGetSymbolAddress((void**)&ath,  g_at_hi);
    cudaGetSymbolAddress((void**)&atl,  g_at_lo);
    cudaGetSymbolAddress((void**)&ach,  g_ac_hi);
    cudaGetSymbolAddress((void**)&acl,  g_ac_lo);
    cudaGetSymbolAddress((void**)&wth,  g_wt_hi);
    cudaGetSymbolAddress((void**)&wtl,  g_wt_lo);

    int flash_smem = (int)sizeof(FlashSmem);
    cudaFuncSetAttribute(flash_kernel, cudaFuncAttributeMaxDynamicSharedMemorySize, flash_smem);
    cudaFuncSetAttribute(gemm_bf16x2, cudaFuncAttributeMaxDynamicSharedMemorySize, GEMM_SMEM);

    // fused one-shot weight prep (transpose + bf16x2 split, all 8 matrices)
    prep_weights<<<2 * TILES_PER_LAYER, dim3(32, 8)>>>(
        w_qkv, w_o, w_gate_up, w_down, wth, wtl);

    embed_kernel<<<Tc, 256>>>(input_ids, embed, res);

    for (int l = 0; l < Lc; l++) {
        __nv_bfloat16* wh = wth + (size_t)l * WT_PER_L;
        __nv_bfloat16* wl = wtl + (size_t)l * WT_PER_L;

        addnorm_kernel<<<Tc, 256>>>(res, l == 0 ? nullptr : hbuf,
                                    ln1_w + (size_t)l * Hc, nullptr, hnh, hnl);

        gemm_bf16x2<<<dim3(Tc / 128, QKVN / 128), 256, GEMM_SMEM>>>(
            hnh, hnl, wh + WT_QKV_OFF, wl + WT_QKV_OFF, qkv, nullptr, Tc, QKVN, Hc);

        rope_kernel<<<Tc, 128>>>(qkv, positions, kc, vc);

        flash_kernel<<<dim3(Sc / 64, NHc, Bc), 256, flash_smem>>>(qkv, kc, vc, ath, atl);

        gemm_bf16x2<<<dim3(Tc / 128, Hc / 128), 256, GEMM_SMEM>>>(
            ath, atl, wh + WT_O_OFF, wl + WT_O_OFF, res, res, Tc, Hc, Hc);

        addnorm_kernel<<<Tc, 256>>>(res, nullptr, ln2_w + (size_t)l * Hc, nullptr, hnh, hnl);

        gemm_bf16x2<<<dim3(Tc / 128, GUN / 128), 256, GEMM_SMEM>>>(
            hnh, hnl, wh + WT_GU_OFF, wl + WT_GU_OFF, gu, nullptr, Tc, GUN, Hc);

        swiglu_kernel<<<(Tc * (size_t)Ic) / 256, 256>>>(gu, ach, acl);

        gemm_bf16x2<<<dim3(Tc / 128, Hc / 128), 256, GEMM_SMEM>>>(
            ach, acl, wh + WT_DN_OFF, wl + WT_DN_OFF, hbuf, nullptr, Tc, Hc, Ic);
    }

    addnorm_kernel<<<Tc, 256>>>(res, hbuf, norm_w, out, nullptr, nullptr);
}